// round 1
// baseline (speedup 1.0000x reference)
#include <cuda_runtime.h>
#include <cuda_bf16.h>
#include <math.h>

#define NNODES 100000
#define NEDGES 1600000
#define HDIM   128
#define NL     3

// ---------------- scratch (no allocations allowed) ----------------
__device__ float g_x  [(size_t)NNODES * HDIM];      // current x / layer_info
__device__ float g_agg[(size_t)NNODES * HDIM];      // agg, reused as t1
__device__ float g_h  [(size_t)NNODES * HDIM];      // gru output, reused as head t2
__device__ float g_gi [(size_t)NNODES * 3 * HDIM];
__device__ float g_gh [(size_t)NNODES * 3 * HDIM];

// ---------------- zero ----------------
__global__ void k_zero4(float4* p, int n4) {
    int i = blockIdx.x * blockDim.x + threadIdx.x;
    if (i < n4) p[i] = make_float4(0.f, 0.f, 0.f, 0.f);
}

// ---------------- SpMM: out[dst] += w * x[src], warp per edge ----------------
__global__ void k_spmm(const int* __restrict__ dst, const int* __restrict__ src,
                       const float* __restrict__ ew, const float* __restrict__ x,
                       float* __restrict__ agg, int E) {
    int widx = (blockIdx.x * blockDim.x + threadIdx.x) >> 5;
    int lane = threadIdx.x & 31;
    if (widx >= E) return;
    int s = src[widx];
    int d = dst[widx];
    float w = ew[widx];
    float4 v = reinterpret_cast<const float4*>(x + (size_t)s * HDIM)[lane];
    float* o = agg + (size_t)d * HDIM + lane * 4;
    atomicAdd(o + 0, w * v.x);
    atomicAdd(o + 1, w * v.y);
    atomicAdd(o + 2, w * v.z);
    atomicAdd(o + 3, w * v.w);
}

// ---------------- GEMM: C[M,Ncol] = act(A[M,128] @ W[Ncol,128]^T + bias) ----------------
#define BM 64
#define BN 128
#define BK 32

template <bool RELU>
__global__ __launch_bounds__(256) void k_gemm(
    const float* __restrict__ A, const float* __restrict__ W,
    const float* __restrict__ bias, float* __restrict__ C,
    int M, int Ncol)
{
    __shared__ float As[BK][BM + 1];    // [32][65]  As[k][m]
    __shared__ float Bs[BK][BN + 4];    // [32][132] Bs[k][n] = W[n0+n][k0+k]

    const int tid = threadIdx.x;
    const int tx = tid & 15;       // 16 col groups (8 cols each)
    const int ty = tid >> 4;       // 16 row groups (4 rows each)
    const int m0 = blockIdx.x * BM;
    const int n0 = blockIdx.y * BN;

    const int kl = tid & 31;       // load lane: k within chunk
    const int rl = tid >> 5;       // load row group 0..7

    float acc[4][8];
#pragma unroll
    for (int i = 0; i < 4; i++)
#pragma unroll
        for (int j = 0; j < 8; j++) acc[i][j] = 0.f;

    for (int k0 = 0; k0 < HDIM; k0 += BK) {
        // load A tile (64 x 32) -> As[k][m]
#pragma unroll
        for (int p = 0; p < 8; p++) {
            int m = rl + p * 8;
            int gm = m0 + m;
            float v = 0.f;
            if (gm < M) v = A[(size_t)gm * HDIM + k0 + kl];
            As[kl][m] = v;
        }
        // load W tile (128 x 32) -> Bs[k][n]
#pragma unroll
        for (int p = 0; p < 16; p++) {
            int n = rl + p * 8;
            Bs[kl][n] = W[(size_t)(n0 + n) * HDIM + k0 + kl];
        }
        __syncthreads();

#pragma unroll
        for (int k = 0; k < BK; k++) {
            float a[4], b[8];
#pragma unroll
            for (int i = 0; i < 4; i++) a[i] = As[k][ty * 4 + i];
#pragma unroll
            for (int j = 0; j < 8; j++) b[j] = Bs[k][tx * 8 + j];
#pragma unroll
            for (int i = 0; i < 4; i++)
#pragma unroll
                for (int j = 0; j < 8; j++) acc[i][j] = fmaf(a[i], b[j], acc[i][j]);
        }
        __syncthreads();
    }

#pragma unroll
    for (int i = 0; i < 4; i++) {
        int gm = m0 + ty * 4 + i;
        if (gm >= M) continue;
        float* crow = C + (size_t)gm * Ncol + n0 + tx * 8;
#pragma unroll
        for (int j = 0; j < 8; j++) {
            float v = acc[i][j] + bias[n0 + tx * 8 + j];
            if (RELU) v = fmaxf(v, 0.f);
            crow[j] = v;
        }
    }
}

// ---------------- GRU elementwise ----------------
__device__ __forceinline__ float sigm(float x) { return 1.f / (1.f + expf(-x)); }

__global__ void k_gru(const float* __restrict__ gi, const float* __restrict__ gh,
                      const float* __restrict__ li, float* __restrict__ h, int total) {
    int i = blockIdx.x * blockDim.x + threadIdx.x;
    if (i >= total) return;
    int n = i >> 7;
    int j = i & 127;
    const float* a = gi + (size_t)n * 384;
    const float* b = gh + (size_t)n * 384;
    float r = sigm(a[j] + b[j]);
    float z = sigm(a[128 + j] + b[128 + j]);
    float nn = tanhf(a[256 + j] + r * b[256 + j]);
    float l = li[i];
    h[i] = (1.f - z) * nn + z * l;
}

// ---------------- row norm: x /= sqrt(1 + sum x^2), warp per row ----------------
__global__ void k_norm(float* __restrict__ x, int M) {
    int row = (blockIdx.x * blockDim.x + threadIdx.x) >> 5;
    int lane = threadIdx.x & 31;
    if (row >= M) return;
    float4* p = reinterpret_cast<float4*>(x + (size_t)row * HDIM);
    float4 v = p[lane];
    float s = v.x * v.x + v.y * v.y + v.z * v.z + v.w * v.w;
#pragma unroll
    for (int o = 16; o; o >>= 1) s += __shfl_xor_sync(0xffffffffu, s, o);
    float inv = rsqrtf(1.f + s);
    v.x *= inv; v.y *= inv; v.z *= inv; v.w *= inv;
    p[lane] = v;
}

// ---------------- head: tmp = t @ w2^T + b2; log_softmax & softmax. warp per node ----------------
template <int C>
__global__ void k_head(const float* __restrict__ t, const float* __restrict__ w2,
                       const float* __restrict__ b2,
                       float* __restrict__ out_log, float* __restrict__ out_soft, int M) {
    int node = (blockIdx.x * blockDim.x + threadIdx.x) >> 5;
    int lane = threadIdx.x & 31;
    if (node >= M) return;
    float4 v = reinterpret_cast<const float4*>(t + (size_t)node * HDIM)[lane];
    float myval = 0.f;
#pragma unroll
    for (int c = 0; c < C; c++) {
        float4 w = reinterpret_cast<const float4*>(w2 + (size_t)c * HDIM)[lane];
        float p = v.x * w.x + v.y * w.y + v.z * w.z + v.w * w.w;
#pragma unroll
        for (int o = 16; o; o >>= 1) p += __shfl_xor_sync(0xffffffffu, p, o);
        if (lane == c) myval = p + b2[c];
    }
    float m = (lane < C) ? myval : -INFINITY;
#pragma unroll
    for (int o = 16; o; o >>= 1) m = fmaxf(m, __shfl_xor_sync(0xffffffffu, m, o));
    float e = (lane < C) ? expf(myval - m) : 0.f;
    float s = e;
#pragma unroll
    for (int o = 16; o; o >>= 1) s += __shfl_xor_sync(0xffffffffu, s, o);
    if (lane < C) {
        out_log [(size_t)node * C + lane] = myval - m - logf(s);
        out_soft[(size_t)node * C + lane] = e / s;
    }
}

// ---------------- launch ----------------
extern "C" void kernel_launch(void* const* d_in, const int* in_sizes, int n_in,
                              void* d_out, int out_size) {
    const float* features = (const float*)d_in[0];
    const int*   eidx     = (const int*)  d_in[1];   // [2,E]: row0=dst, row1=src
    const float* ew       = (const float*)d_in[2];
    const float* w1       = (const float*)d_in[3];
    const float* b1       = (const float*)d_in[4];
    const float* gin_w1   = (const float*)d_in[5];
    const float* gin_b1   = (const float*)d_in[6];
    const float* gin_w2   = (const float*)d_in[7];
    const float* gin_b2   = (const float*)d_in[8];
    const float* gru_wih  = (const float*)d_in[9];
    const float* gru_whh  = (const float*)d_in[10];
    const float* gru_bih  = (const float*)d_in[11];
    const float* gru_bhh  = (const float*)d_in[12];
    const float* head_w1  = (const float*)d_in[13];
    const float* head_b1  = (const float*)d_in[14];
    const float* hw2_0    = (const float*)d_in[15];
    const float* hb2_0    = (const float*)d_in[16];
    const float* hw2_1    = (const float*)d_in[17];
    const float* hb2_1    = (const float*)d_in[18];
    const float* hw2_2    = (const float*)d_in[19];
    const float* hb2_2    = (const float*)d_in[20];

    float* out = (float*)d_out;

    float *p_x, *p_agg, *p_h, *p_gi, *p_gh;
    cudaGetSymbolAddress((void**)&p_x,   g_x);
    cudaGetSymbolAddress((void**)&p_agg, g_agg);
    cudaGetSymbolAddress((void**)&p_h,   g_h);
    cudaGetSymbolAddress((void**)&p_gi,  g_gi);
    cudaGetSymbolAddress((void**)&p_gh,  g_gh);

    const int M = NNODES;
    const int E = NEDGES;
    const int gemm_gx = (M + BM - 1) / BM;                 // 1563
    const int warp_blocks = (M * 32 + 255) / 256;          // 12500
    const int elem_blocks = (M * HDIM + 255) / 256;        // 50000
    const int zero_blocks = (M * HDIM / 4 + 255) / 256;    // 12500
    const int spmm_blocks = (E * 32 + 255) / 256;          // 200000

    const int NH = M * HDIM;

    // output offsets (tuple order: log0, log1, log2, soft0, soft1, soft2)
    const size_t o_log0 = 0;
    const size_t o_log1 = (size_t)M * 2;
    const size_t o_log2 = (size_t)M * 8;
    const size_t o_soft = (size_t)M * 29;

    // x = relu(features @ w1^T + b1)
    k_gemm<true><<<dim3(gemm_gx, 1), 256>>>(features, w1, b1, p_x, M, HDIM);

    for (int i = 0; i < NL; i++) {
        // agg = segment_sum(ew * x[src], dst)
        k_zero4<<<zero_blocks, 256>>>((float4*)p_agg, NH / 4);
        k_spmm<<<spmm_blocks, 256>>>(eidx, eidx + E, ew, p_x, p_agg, E);

        // GRU gates
        k_gemm<false><<<dim3(gemm_gx, 3), 256>>>(p_agg, gru_wih + (size_t)i * 384 * HDIM,
                                                 gru_bih + (size_t)i * 384, p_gi, M, 384);
        k_gemm<false><<<dim3(gemm_gx, 3), 256>>>(p_x,   gru_whh + (size_t)i * 384 * HDIM,
                                                 gru_bhh + (size_t)i * 384, p_gh, M, 384);
        k_gru<<<elem_blocks, 256>>>(p_gi, p_gh, p_x, p_h, NH);

        // GIN MLP: t1 = relu(h @ gw1^T + gb1); x = relu(t1 @ gw2^T + gb2)
        k_gemm<true><<<dim3(gemm_gx, 1), 256>>>(p_h,   gin_w1 + (size_t)i * HDIM * HDIM,
                                                gin_b1 + (size_t)i * HDIM, p_agg, M, HDIM);
        k_gemm<true><<<dim3(gemm_gx, 1), 256>>>(p_agg, gin_w2 + (size_t)i * HDIM * HDIM,
                                                gin_b2 + (size_t)i * HDIM, p_x, M, HDIM);
        // x /= sqrt(1 + ||x||^2)
        k_norm<<<warp_blocks, 256>>>(p_x, M);

        // head: t2 = relu(x @ hw1^T + hb1); logits -> log_softmax / softmax
        k_gemm<true><<<dim3(gemm_gx, 1), 256>>>(p_x, head_w1 + (size_t)i * HDIM * HDIM,
                                                head_b1 + (size_t)i * HDIM, p_h, M, HDIM);
        if (i == 0)
            k_head<2><<<warp_blocks, 256>>>(p_h, hw2_0, hb2_0,
                                            out + o_log0, out + o_soft + 0, M);
        else if (i == 1)
            k_head<6><<<warp_blocks, 256>>>(p_h, hw2_1, hb2_1,
                                            out + o_log1, out + o_soft + (size_t)M * 2, M);
        else
            k_head<21><<<warp_blocks, 256>>>(p_h, hw2_2, hb2_2,
                                             out + o_log2, out + o_soft + (size_t)M * 8, M);
    }
}

// round 2
// speedup vs baseline: 1.2147x; 1.2147x over previous
#include <cuda_runtime.h>
#include <cuda_bf16.h>
#include <math.h>

#define NNODES 100000
#define NEDGES 1600000
#define HDIM   128
#define NL     3
#define SCAN_B 512
#define NSCANB ((NNODES + SCAN_B - 1) / SCAN_B)   // 196

// ---------------- scratch (no allocations allowed) ----------------
__device__ float g_x  [(size_t)NNODES * HDIM];
__device__ float g_agg[(size_t)NNODES * HDIM];
__device__ float g_h  [(size_t)NNODES * HDIM];
__device__ float g_gi [(size_t)NNODES * 3 * HDIM];
__device__ float g_gh [(size_t)NNODES * 3 * HDIM];
// CSR scratch
__device__ int   g_rowptr[NNODES + 1];
__device__ int   g_cursor[NNODES];
__device__ int   g_blocksum[NSCANB];
__device__ int   g_blockoff[NSCANB];
__device__ int   g_csr_src[NEDGES];
__device__ float g_csr_w  [NEDGES];

// ---------------- CSR build ----------------
__global__ void k_deg_zero(int* deg, int n) {
    int i = blockIdx.x * blockDim.x + threadIdx.x;
    if (i < n) deg[i] = 0;
}

__global__ void k_hist(const int* __restrict__ dst, int* __restrict__ deg, int E) {
    int i = blockIdx.x * blockDim.x + threadIdx.x;
    if (i < E) atomicAdd(&deg[dst[i]], 1);
}

// block-local exclusive scan of degrees -> rowptr(local); blocksum per block
__global__ __launch_bounds__(SCAN_B) void k_scan_local(const int* __restrict__ deg,
                                                       int* __restrict__ rowptr,
                                                       int* __restrict__ blocksum, int n) {
    __shared__ int s[SCAN_B];
    int tid = threadIdx.x;
    int i = blockIdx.x * SCAN_B + tid;
    int v = (i < n) ? deg[i] : 0;
    s[tid] = v;
    __syncthreads();
    // Hillis-Steele inclusive scan
    for (int off = 1; off < SCAN_B; off <<= 1) {
        int t = (tid >= off) ? s[tid - off] : 0;
        __syncthreads();
        s[tid] += t;
        __syncthreads();
    }
    if (i < n) rowptr[i] = s[tid] - v;   // exclusive
    if (tid == SCAN_B - 1) blocksum[blockIdx.x] = s[tid];
}

__global__ void k_scan_block(const int* __restrict__ blocksum, int* __restrict__ blockoff,
                             int* __restrict__ rowptr, int nblk, int n) {
    if (threadIdx.x == 0 && blockIdx.x == 0) {
        int acc = 0;
        for (int b = 0; b < nblk; b++) { blockoff[b] = acc; acc += blocksum[b]; }
        rowptr[n] = acc;
    }
}

__global__ void k_scan_add(int* __restrict__ rowptr, int* __restrict__ cursor,
                           const int* __restrict__ blockoff, int n) {
    int i = blockIdx.x * blockDim.x + threadIdx.x;
    if (i < n) {
        int v = rowptr[i] + blockoff[i / SCAN_B];
        rowptr[i] = v;
        cursor[i] = v;
    }
}

__global__ void k_scatter(const int* __restrict__ dst, const int* __restrict__ src,
                          const float* __restrict__ ew, int* __restrict__ cursor,
                          int* __restrict__ csr_src, float* __restrict__ csr_w, int E) {
    int i = blockIdx.x * blockDim.x + threadIdx.x;
    if (i < E) {
        int pos = atomicAdd(&cursor[dst[i]], 1);
        csr_src[pos] = src[i];
        csr_w[pos] = ew[i];
    }
}

// ---------------- SpMM (CSR, warp per node, no atomics) ----------------
__global__ __launch_bounds__(256) void k_spmm_csr(
    const int* __restrict__ rowptr, const int* __restrict__ csr_src,
    const float* __restrict__ csr_w, const float* __restrict__ x,
    float* __restrict__ agg, int n) {
    int row = (blockIdx.x * blockDim.x + threadIdx.x) >> 5;
    int lane = threadIdx.x & 31;
    if (row >= n) return;
    int e = rowptr[row];
    int end = rowptr[row + 1];
    const float4* x4 = reinterpret_cast<const float4*>(x);
    float4 a0 = make_float4(0.f, 0.f, 0.f, 0.f);
    float4 a1 = make_float4(0.f, 0.f, 0.f, 0.f);
    for (; e + 1 < end; e += 2) {
        int s0 = csr_src[e];
        int s1 = csr_src[e + 1];
        float w0 = csr_w[e];
        float w1 = csr_w[e + 1];
        float4 v0 = x4[(size_t)s0 * 32 + lane];
        float4 v1 = x4[(size_t)s1 * 32 + lane];
        a0.x = fmaf(w0, v0.x, a0.x); a0.y = fmaf(w0, v0.y, a0.y);
        a0.z = fmaf(w0, v0.z, a0.z); a0.w = fmaf(w0, v0.w, a0.w);
        a1.x = fmaf(w1, v1.x, a1.x); a1.y = fmaf(w1, v1.y, a1.y);
        a1.z = fmaf(w1, v1.z, a1.z); a1.w = fmaf(w1, v1.w, a1.w);
    }
    if (e < end) {
        int s0 = csr_src[e];
        float w0 = csr_w[e];
        float4 v0 = x4[(size_t)s0 * 32 + lane];
        a0.x = fmaf(w0, v0.x, a0.x); a0.y = fmaf(w0, v0.y, a0.y);
        a0.z = fmaf(w0, v0.z, a0.z); a0.w = fmaf(w0, v0.w, a0.w);
    }
    a0.x += a1.x; a0.y += a1.y; a0.z += a1.z; a0.w += a1.w;
    reinterpret_cast<float4*>(agg)[(size_t)row * 32 + lane] = a0;
}

// ---------------- GEMM: C[M,Ncol] = act(A[M,128] @ W[Ncol,128]^T + bias) ----------------
#define BM 128
#define BN 128
#define BK 32
#define SPAD 4   // row stride BM+SPAD = 132 (16B aligned, bank-shifted)

template <bool RELU>
__global__ __launch_bounds__(256, 2) void k_gemm(
    const float* __restrict__ A, const float* __restrict__ W,
    const float* __restrict__ bias, float* __restrict__ C,
    int M, int Ncol)
{
    __shared__ float As[BK][BM + SPAD];
    __shared__ float Bs[BK][BN + SPAD];

    const int tid = threadIdx.x;
    const int tx = tid & 15;
    const int ty = tid >> 4;
    const int m0 = blockIdx.x * BM;
    const int n0 = blockIdx.y * BN;

    // loader indexing: 128 rows x 8 k-quads = 1024 float4 per tile; 4 per thread
    const int lrow = tid >> 3;          // 0..31
    const int lkq  = (tid & 7) * 4;     // k-quad start

    float acc[8][8];
#pragma unroll
    for (int i = 0; i < 8; i++)
#pragma unroll
        for (int j = 0; j < 8; j++) acc[i][j] = 0.f;

    for (int k0 = 0; k0 < HDIM; k0 += BK) {
#pragma unroll
        for (int p = 0; p < 4; p++) {
            int row = lrow + p * 32;
            int gm = m0 + row;
            float4 va = make_float4(0.f, 0.f, 0.f, 0.f);
            if (gm < M) va = *reinterpret_cast<const float4*>(A + (size_t)gm * HDIM + k0 + lkq);
            As[lkq + 0][row] = va.x; As[lkq + 1][row] = va.y;
            As[lkq + 2][row] = va.z; As[lkq + 3][row] = va.w;
            float4 vb = *reinterpret_cast<const float4*>(W + (size_t)(n0 + row) * HDIM + k0 + lkq);
            Bs[lkq + 0][row] = vb.x; Bs[lkq + 1][row] = vb.y;
            Bs[lkq + 2][row] = vb.z; Bs[lkq + 3][row] = vb.w;
        }
        __syncthreads();

#pragma unroll
        for (int k = 0; k < BK; k++) {
            float a[8], b[8];
            *reinterpret_cast<float4*>(a)     = *reinterpret_cast<const float4*>(&As[k][ty * 8]);
            *reinterpret_cast<float4*>(a + 4) = *reinterpret_cast<const float4*>(&As[k][ty * 8 + 4]);
            *reinterpret_cast<float4*>(b)     = *reinterpret_cast<const float4*>(&Bs[k][tx * 8]);
            *reinterpret_cast<float4*>(b + 4) = *reinterpret_cast<const float4*>(&Bs[k][tx * 8 + 4]);
#pragma unroll
            for (int i = 0; i < 8; i++)
#pragma unroll
                for (int j = 0; j < 8; j++) acc[i][j] = fmaf(a[i], b[j], acc[i][j]);
        }
        __syncthreads();
    }

    float bv[8];
#pragma unroll
    for (int j = 0; j < 8; j++) bv[j] = bias[n0 + tx * 8 + j];

#pragma unroll
    for (int i = 0; i < 8; i++) {
        int gm = m0 + ty * 8 + i;
        if (gm >= M) continue;
        float o[8];
#pragma unroll
        for (int j = 0; j < 8; j++) {
            float v = acc[i][j] + bv[j];
            if (RELU) v = fmaxf(v, 0.f);
            o[j] = v;
        }
        float* crow = C + (size_t)gm * Ncol + n0 + tx * 8;
        *reinterpret_cast<float4*>(crow)     = *reinterpret_cast<float4*>(o);
        *reinterpret_cast<float4*>(crow + 4) = *reinterpret_cast<float4*>(o + 4);
    }
}

// ---------------- GRU elementwise ----------------
__device__ __forceinline__ float sigm(float x) { return 1.f / (1.f + expf(-x)); }

__global__ void k_gru(const float* __restrict__ gi, const float* __restrict__ gh,
                      const float* __restrict__ li, float* __restrict__ h, int total) {
    int i = blockIdx.x * blockDim.x + threadIdx.x;
    if (i >= total) return;
    int n = i >> 7;
    int j = i & 127;
    const float* a = gi + (size_t)n * 384;
    const float* b = gh + (size_t)n * 384;
    float r = sigm(a[j] + b[j]);
    float z = sigm(a[128 + j] + b[128 + j]);
    float nn = tanhf(a[256 + j] + r * b[256 + j]);
    float l = li[i];
    h[i] = (1.f - z) * nn + z * l;
}

// ---------------- row norm ----------------
__global__ void k_norm(float* __restrict__ x, int M) {
    int row = (blockIdx.x * blockDim.x + threadIdx.x) >> 5;
    int lane = threadIdx.x & 31;
    if (row >= M) return;
    float4* p = reinterpret_cast<float4*>(x + (size_t)row * HDIM);
    float4 v = p[lane];
    float s = v.x * v.x + v.y * v.y + v.z * v.z + v.w * v.w;
#pragma unroll
    for (int o = 16; o; o >>= 1) s += __shfl_xor_sync(0xffffffffu, s, o);
    float inv = rsqrtf(1.f + s);
    v.x *= inv; v.y *= inv; v.z *= inv; v.w *= inv;
    p[lane] = v;
}

// ---------------- head ----------------
template <int C>
__global__ void k_head(const float* __restrict__ t, const float* __restrict__ w2,
                       const float* __restrict__ b2,
                       float* __restrict__ out_log, float* __restrict__ out_soft, int M) {
    int node = (blockIdx.x * blockDim.x + threadIdx.x) >> 5;
    int lane = threadIdx.x & 31;
    if (node >= M) return;
    float4 v = reinterpret_cast<const float4*>(t + (size_t)node * HDIM)[lane];
    float myval = 0.f;
#pragma unroll
    for (int c = 0; c < C; c++) {
        float4 w = reinterpret_cast<const float4*>(w2 + (size_t)c * HDIM)[lane];
        float p = v.x * w.x + v.y * w.y + v.z * w.z + v.w * w.w;
#pragma unroll
        for (int o = 16; o; o >>= 1) p += __shfl_xor_sync(0xffffffffu, p, o);
        if (lane == c) myval = p + b2[c];
    }
    float m = (lane < C) ? myval : -INFINITY;
#pragma unroll
    for (int o = 16; o; o >>= 1) m = fmaxf(m, __shfl_xor_sync(0xffffffffu, m, o));
    float e = (lane < C) ? expf(myval - m) : 0.f;
    float s = e;
#pragma unroll
    for (int o = 16; o; o >>= 1) s += __shfl_xor_sync(0xffffffffu, s, o);
    if (lane < C) {
        out_log [(size_t)node * C + lane] = myval - m - logf(s);
        out_soft[(size_t)node * C + lane] = e / s;
    }
}

// ---------------- launch ----------------
extern "C" void kernel_launch(void* const* d_in, const int* in_sizes, int n_in,
                              void* d_out, int out_size) {
    const float* features = (const float*)d_in[0];
    const int*   eidx     = (const int*)  d_in[1];
    const float* ew       = (const float*)d_in[2];
    const float* w1       = (const float*)d_in[3];
    const float* b1       = (const float*)d_in[4];
    const float* gin_w1   = (const float*)d_in[5];
    const float* gin_b1   = (const float*)d_in[6];
    const float* gin_w2   = (const float*)d_in[7];
    const float* gin_b2   = (const float*)d_in[8];
    const float* gru_wih  = (const float*)d_in[9];
    const float* gru_whh  = (const float*)d_in[10];
    const float* gru_bih  = (const float*)d_in[11];
    const float* gru_bhh  = (const float*)d_in[12];
    const float* head_w1  = (const float*)d_in[13];
    const float* head_b1  = (const float*)d_in[14];
    const float* hw2_0    = (const float*)d_in[15];
    const float* hb2_0    = (const float*)d_in[16];
    const float* hw2_1    = (const float*)d_in[17];
    const float* hb2_1    = (const float*)d_in[18];
    const float* hw2_2    = (const float*)d_in[19];
    const float* hb2_2    = (const float*)d_in[20];

    float* out = (float*)d_out;

    float *p_x, *p_agg, *p_h, *p_gi, *p_gh, *p_csr_w;
    int *p_rowptr, *p_cursor, *p_bsum, *p_boff, *p_csr_src;
    cudaGetSymbolAddress((void**)&p_x,      g_x);
    cudaGetSymbolAddress((void**)&p_agg,    g_agg);
    cudaGetSymbolAddress((void**)&p_h,      g_h);
    cudaGetSymbolAddress((void**)&p_gi,     g_gi);
    cudaGetSymbolAddress((void**)&p_gh,     g_gh);
    cudaGetSymbolAddress((void**)&p_rowptr, g_rowptr);
    cudaGetSymbolAddress((void**)&p_cursor, g_cursor);
    cudaGetSymbolAddress((void**)&p_bsum,   g_blocksum);
    cudaGetSymbolAddress((void**)&p_boff,   g_blockoff);
    cudaGetSymbolAddress((void**)&p_csr_src,g_csr_src);
    cudaGetSymbolAddress((void**)&p_csr_w,  g_csr_w);

    const int M = NNODES;
    const int E = NEDGES;
    const int gemm_gx = (M + BM - 1) / BM;                 // 782
    const int warp_blocks = (M * 32 + 255) / 256;          // 12500
    const int elem_blocks = (M * HDIM + 255) / 256;        // 50000
    const int edge_blocks = (E + 255) / 256;               // 6250
    const int node_blocks = (M + 255) / 256;               // 391
    const int NH = M * HDIM;

    const int* e_dst = eidx;
    const int* e_src = eidx + E;

    // output offsets (tuple order: log0, log1, log2, soft0, soft1, soft2)
    const size_t o_log0 = 0;
    const size_t o_log1 = (size_t)M * 2;
    const size_t o_log2 = (size_t)M * 8;
    const size_t o_soft = (size_t)M * 29;

    // ---- build CSR (deg -> rowptr -> scatter) ----
    k_deg_zero<<<node_blocks, 256>>>(p_cursor, M);   // use cursor as deg temp
    k_hist<<<edge_blocks, 256>>>(e_dst, p_cursor, E);
    k_scan_local<<<NSCANB, SCAN_B>>>(p_cursor, p_rowptr, p_bsum, M);
    k_scan_block<<<1, 32>>>(p_bsum, p_boff, p_rowptr, NSCANB, M);
    k_scan_add<<<node_blocks, 256>>>(p_rowptr, p_cursor, p_boff, M);
    k_scatter<<<edge_blocks, 256>>>(e_dst, e_src, ew, p_cursor, p_csr_src, p_csr_w, E);

    // x = relu(features @ w1^T + b1)
    k_gemm<true><<<dim3(gemm_gx, 1), 256>>>(features, w1, b1, p_x, M, HDIM);

    for (int i = 0; i < NL; i++) {
        // agg = segment_sum(ew * x[src], dst)
        k_spmm_csr<<<warp_blocks, 256>>>(p_rowptr, p_csr_src, p_csr_w, p_x, p_agg, M);

        // GRU gates
        k_gemm<false><<<dim3(gemm_gx, 3), 256>>>(p_agg, gru_wih + (size_t)i * 384 * HDIM,
                                                 gru_bih + (size_t)i * 384, p_gi, M, 384);
        k_gemm<false><<<dim3(gemm_gx, 3), 256>>>(p_x,   gru_whh + (size_t)i * 384 * HDIM,
                                                 gru_bhh + (size_t)i * 384, p_gh, M, 384);
        k_gru<<<elem_blocks, 256>>>(p_gi, p_gh, p_x, p_h, NH);

        // GIN MLP
        k_gemm<true><<<dim3(gemm_gx, 1), 256>>>(p_h,   gin_w1 + (size_t)i * HDIM * HDIM,
                                                gin_b1 + (size_t)i * HDIM, p_agg, M, HDIM);
        k_gemm<true><<<dim3(gemm_gx, 1), 256>>>(p_agg, gin_w2 + (size_t)i * HDIM * HDIM,
                                                gin_b2 + (size_t)i * HDIM, p_x, M, HDIM);
        k_norm<<<warp_blocks, 256>>>(p_x, M);

        // head
        k_gemm<true><<<dim3(gemm_gx, 1), 256>>>(p_x, head_w1 + (size_t)i * HDIM * HDIM,
                                                head_b1 + (size_t)i * HDIM, p_h, M, HDIM);
        if (i == 0)
            k_head<2><<<warp_blocks, 256>>>(p_h, hw2_0, hb2_0,
                                            out + o_log0, out + o_soft + 0, M);
        else if (i == 1)
            k_head<6><<<warp_blocks, 256>>>(p_h, hw2_1, hb2_1,
                                            out + o_log1, out + o_soft + (size_t)M * 2, M);
        else
            k_head<21><<<warp_blocks, 256>>>(p_h, hw2_2, hb2_2,
                                             out + o_log2, out + o_soft + (size_t)M * 8, M);
    }
}

// round 3
// speedup vs baseline: 3.4359x; 2.8286x over previous
#include <cuda_runtime.h>
#include <cuda_bf16.h>
#include <math.h>

#define NNODES 100000
#define NEDGES 1600000
#define HDIM   128
#define NL     3
#define SCAN_B 512
#define NSCANB ((NNODES + SCAN_B - 1) / SCAN_B)   // 196

// ---------------- scratch (no allocations allowed) ----------------
__device__ float g_x  [(size_t)NNODES * HDIM];
__device__ float g_agg[(size_t)NNODES * HDIM];
__device__ float g_h  [(size_t)NNODES * HDIM];
__device__ float g_gi [(size_t)NNODES * 3 * HDIM];
__device__ float g_gh [(size_t)NNODES * 3 * HDIM];
// CSR scratch
__device__ int   g_rowptr[NNODES + 1];
__device__ int   g_cursor[NNODES];
__device__ int   g_blocksum[NSCANB];
__device__ int   g_blockoff[NSCANB];
__device__ int   g_csr_src[NEDGES];
__device__ float g_csr_w  [NEDGES];

// ---------------- CSR build ----------------
__global__ void k_deg_zero(int* deg, int n) {
    int i = blockIdx.x * blockDim.x + threadIdx.x;
    if (i < n) deg[i] = 0;
}

__global__ void k_hist(const int* __restrict__ dst, int* __restrict__ deg, int E) {
    int i = blockIdx.x * blockDim.x + threadIdx.x;
    if (i < E) atomicAdd(&deg[dst[i]], 1);
}

__global__ __launch_bounds__(SCAN_B) void k_scan_local(const int* __restrict__ deg,
                                                       int* __restrict__ rowptr,
                                                       int* __restrict__ blocksum, int n) {
    __shared__ int s[SCAN_B];
    int tid = threadIdx.x;
    int i = blockIdx.x * SCAN_B + tid;
    int v = (i < n) ? deg[i] : 0;
    s[tid] = v;
    __syncthreads();
    for (int off = 1; off < SCAN_B; off <<= 1) {
        int t = (tid >= off) ? s[tid - off] : 0;
        __syncthreads();
        s[tid] += t;
        __syncthreads();
    }
    if (i < n) rowptr[i] = s[tid] - v;
    if (tid == SCAN_B - 1) blocksum[blockIdx.x] = s[tid];
}

__global__ void k_scan_block(const int* __restrict__ blocksum, int* __restrict__ blockoff,
                             int* __restrict__ rowptr, int nblk, int n) {
    if (threadIdx.x == 0 && blockIdx.x == 0) {
        int acc = 0;
        for (int b = 0; b < nblk; b++) { blockoff[b] = acc; acc += blocksum[b]; }
        rowptr[n] = acc;
    }
}

__global__ void k_scan_add(int* __restrict__ rowptr, int* __restrict__ cursor,
                           const int* __restrict__ blockoff, int n) {
    int i = blockIdx.x * blockDim.x + threadIdx.x;
    if (i < n) {
        int v = rowptr[i] + blockoff[i / SCAN_B];
        rowptr[i] = v;
        cursor[i] = v;
    }
}

__global__ void k_scatter(const int* __restrict__ dst, const int* __restrict__ src,
                          const float* __restrict__ ew, int* __restrict__ cursor,
                          int* __restrict__ csr_src, float* __restrict__ csr_w, int E) {
    int i = blockIdx.x * blockDim.x + threadIdx.x;
    if (i < E) {
        int pos = atomicAdd(&cursor[dst[i]], 1);
        csr_src[pos] = src[i];
        csr_w[pos] = ew[i];
    }
}

// ---------------- SpMM (CSR, warp per node, no atomics) ----------------
__global__ __launch_bounds__(256) void k_spmm_csr(
    const int* __restrict__ rowptr, const int* __restrict__ csr_src,
    const float* __restrict__ csr_w, const float* __restrict__ x,
    float* __restrict__ agg, int n) {
    int row = (blockIdx.x * blockDim.x + threadIdx.x) >> 5;
    int lane = threadIdx.x & 31;
    if (row >= n) return;
    int e = rowptr[row];
    int end = rowptr[row + 1];
    const float4* x4 = reinterpret_cast<const float4*>(x);
    float4 a0 = make_float4(0.f, 0.f, 0.f, 0.f);
    float4 a1 = make_float4(0.f, 0.f, 0.f, 0.f);
    for (; e + 1 < end; e += 2) {
        int s0 = csr_src[e];
        int s1 = csr_src[e + 1];
        float w0 = csr_w[e];
        float w1 = csr_w[e + 1];
        float4 v0 = x4[(size_t)s0 * 32 + lane];
        float4 v1 = x4[(size_t)s1 * 32 + lane];
        a0.x = fmaf(w0, v0.x, a0.x); a0.y = fmaf(w0, v0.y, a0.y);
        a0.z = fmaf(w0, v0.z, a0.z); a0.w = fmaf(w0, v0.w, a0.w);
        a1.x = fmaf(w1, v1.x, a1.x); a1.y = fmaf(w1, v1.y, a1.y);
        a1.z = fmaf(w1, v1.z, a1.z); a1.w = fmaf(w1, v1.w, a1.w);
    }
    if (e < end) {
        int s0 = csr_src[e];
        float w0 = csr_w[e];
        float4 v0 = x4[(size_t)s0 * 32 + lane];
        a0.x = fmaf(w0, v0.x, a0.x); a0.y = fmaf(w0, v0.y, a0.y);
        a0.z = fmaf(w0, v0.z, a0.z); a0.w = fmaf(w0, v0.w, a0.w);
    }
    a0.x += a1.x; a0.y += a1.y; a0.z += a1.z; a0.w += a1.w;
    reinterpret_cast<float4*>(agg)[(size_t)row * 32 + lane] = a0;
}

// ---------------- TF32 tensor-core GEMM ----------------
// C[M,Ncol] = act(A[M,128] @ W[Ncol,128]^T + bias), tile 128x128, K chunk 32
#define TBK 32
#define KPAD 4     // row stride = 36 floats

__device__ __forceinline__ unsigned f2tf32(float x) {
    unsigned r;
    asm("cvt.rna.tf32.f32 %0, %1;" : "=r"(r) : "f"(x));
    return r;
}

__device__ __forceinline__ void mma_tf32(float* d, const unsigned* a, const unsigned* b) {
    asm volatile(
        "mma.sync.aligned.m16n8k8.row.col.f32.tf32.tf32.f32 "
        "{%0,%1,%2,%3}, {%4,%5,%6,%7}, {%8,%9}, {%0,%1,%2,%3};\n"
        : "+f"(d[0]), "+f"(d[1]), "+f"(d[2]), "+f"(d[3])
        : "r"(a[0]), "r"(a[1]), "r"(a[2]), "r"(a[3]), "r"(b[0]), "r"(b[1]));
}

template <bool RELU>
__global__ __launch_bounds__(256, 2) void k_gemm_t(
    const float* __restrict__ A, const float* __restrict__ W,
    const float* __restrict__ bias, float* __restrict__ C,
    int M, int Ncol)
{
    __shared__ unsigned As[128][TBK + KPAD];   // A (tf32 bits), [m][k]
    __shared__ unsigned Ws[128][TBK + KPAD];   // W (tf32 bits), [n][k]

    const int tid = threadIdx.x;
    const int wid = tid >> 5;
    const int lane = tid & 31;
    const int g = lane >> 2;         // group 0..7
    const int t4 = lane & 3;         // 0..3
    const int wm = wid & 3;          // warp row 0..3 (32 rows each)
    const int wn = wid >> 2;         // warp col 0..1 (64 cols each)
    const int m0 = blockIdx.x * 128;
    const int n0 = blockIdx.y * 128;

    const int lrow = tid >> 3;       // 0..31
    const int lkq  = (tid & 7) * 4;  // 0,4,...,28

    float acc[2][8][4];
#pragma unroll
    for (int i = 0; i < 2; i++)
#pragma unroll
        for (int j = 0; j < 8; j++)
#pragma unroll
            for (int r = 0; r < 4; r++) acc[i][j][r] = 0.f;

    for (int k0 = 0; k0 < HDIM; k0 += TBK) {
        // load + convert A tile (128x32) and W tile (128x32)
#pragma unroll
        for (int p = 0; p < 4; p++) {
            int row = lrow + p * 32;
            int gm = m0 + row;
            float4 va = make_float4(0.f, 0.f, 0.f, 0.f);
            if (gm < M) va = *reinterpret_cast<const float4*>(A + (size_t)gm * HDIM + k0 + lkq);
            As[row][lkq + 0] = f2tf32(va.x);
            As[row][lkq + 1] = f2tf32(va.y);
            As[row][lkq + 2] = f2tf32(va.z);
            As[row][lkq + 3] = f2tf32(va.w);
            float4 vb = *reinterpret_cast<const float4*>(W + (size_t)(n0 + row) * HDIM + k0 + lkq);
            Ws[row][lkq + 0] = f2tf32(vb.x);
            Ws[row][lkq + 1] = f2tf32(vb.y);
            Ws[row][lkq + 2] = f2tf32(vb.z);
            Ws[row][lkq + 3] = f2tf32(vb.w);
        }
        __syncthreads();

#pragma unroll
        for (int ks = 0; ks < 4; ks++) {
            int kb = ks * 8;
            unsigned af[2][4];
#pragma unroll
            for (int i = 0; i < 2; i++) {
                int rb = wm * 32 + i * 16;
                af[i][0] = As[rb + g][kb + t4];
                af[i][1] = As[rb + g + 8][kb + t4];
                af[i][2] = As[rb + g][kb + t4 + 4];
                af[i][3] = As[rb + g + 8][kb + t4 + 4];
            }
            unsigned bf[8][2];
#pragma unroll
            for (int j = 0; j < 8; j++) {
                int nb = wn * 64 + j * 8;
                bf[j][0] = Ws[nb + g][kb + t4];
                bf[j][1] = Ws[nb + g][kb + t4 + 4];
            }
#pragma unroll
            for (int i = 0; i < 2; i++)
#pragma unroll
                for (int j = 0; j < 8; j++)
                    mma_tf32(acc[i][j], af[i], bf[j]);
        }
        __syncthreads();
    }

    // epilogue: C[row][col] from c-fragment layout
#pragma unroll
    for (int i = 0; i < 2; i++) {
        int row_lo = m0 + wm * 32 + i * 16 + g;
        int row_hi = row_lo + 8;
#pragma unroll
        for (int j = 0; j < 8; j++) {
            int col = n0 + wn * 64 + j * 8 + 2 * t4;
            float b0 = bias[col];
            float b1 = bias[col + 1];
            if (row_lo < M) {
                float v0 = acc[i][j][0] + b0;
                float v1 = acc[i][j][1] + b1;
                if (RELU) { v0 = fmaxf(v0, 0.f); v1 = fmaxf(v1, 0.f); }
                *reinterpret_cast<float2*>(C + (size_t)row_lo * Ncol + col) = make_float2(v0, v1);
            }
            if (row_hi < M) {
                float v2 = acc[i][j][2] + b0;
                float v3 = acc[i][j][3] + b1;
                if (RELU) { v2 = fmaxf(v2, 0.f); v3 = fmaxf(v3, 0.f); }
                *reinterpret_cast<float2*>(C + (size_t)row_hi * Ncol + col) = make_float2(v2, v3);
            }
        }
    }
}

// ---------------- GRU elementwise ----------------
__device__ __forceinline__ float sigm(float x) { return 1.f / (1.f + expf(-x)); }

__global__ void k_gru(const float* __restrict__ gi, const float* __restrict__ gh,
                      const float* __restrict__ li, float* __restrict__ h, int total) {
    int i = blockIdx.x * blockDim.x + threadIdx.x;
    if (i >= total) return;
    int n = i >> 7;
    int j = i & 127;
    const float* a = gi + (size_t)n * 384;
    const float* b = gh + (size_t)n * 384;
    float r = sigm(a[j] + b[j]);
    float z = sigm(a[128 + j] + b[128 + j]);
    float nn = tanhf(a[256 + j] + r * b[256 + j]);
    float l = li[i];
    h[i] = (1.f - z) * nn + z * l;
}

// ---------------- row norm ----------------
__global__ void k_norm(float* __restrict__ x, int M) {
    int row = (blockIdx.x * blockDim.x + threadIdx.x) >> 5;
    int lane = threadIdx.x & 31;
    if (row >= M) return;
    float4* p = reinterpret_cast<float4*>(x + (size_t)row * HDIM);
    float4 v = p[lane];
    float s = v.x * v.x + v.y * v.y + v.z * v.z + v.w * v.w;
#pragma unroll
    for (int o = 16; o; o >>= 1) s += __shfl_xor_sync(0xffffffffu, s, o);
    float inv = rsqrtf(1.f + s);
    v.x *= inv; v.y *= inv; v.z *= inv; v.w *= inv;
    p[lane] = v;
}

// ---------------- head ----------------
template <int C>
__global__ void k_head(const float* __restrict__ t, const float* __restrict__ w2,
                       const float* __restrict__ b2,
                       float* __restrict__ out_log, float* __restrict__ out_soft, int M) {
    int node = (blockIdx.x * blockDim.x + threadIdx.x) >> 5;
    int lane = threadIdx.x & 31;
    if (node >= M) return;
    float4 v = reinterpret_cast<const float4*>(t + (size_t)node * HDIM)[lane];
    float myval = 0.f;
#pragma unroll
    for (int c = 0; c < C; c++) {
        float4 w = reinterpret_cast<const float4*>(w2 + (size_t)c * HDIM)[lane];
        float p = v.x * w.x + v.y * w.y + v.z * w.z + v.w * w.w;
#pragma unroll
        for (int o = 16; o; o >>= 1) p += __shfl_xor_sync(0xffffffffu, p, o);
        if (lane == c) myval = p + b2[c];
    }
    float m = (lane < C) ? myval : -INFINITY;
#pragma unroll
    for (int o = 16; o; o >>= 1) m = fmaxf(m, __shfl_xor_sync(0xffffffffu, m, o));
    float e = (lane < C) ? expf(myval - m) : 0.f;
    float s = e;
#pragma unroll
    for (int o = 16; o; o >>= 1) s += __shfl_xor_sync(0xffffffffu, s, o);
    if (lane < C) {
        out_log [(size_t)node * C + lane] = myval - m - logf(s);
        out_soft[(size_t)node * C + lane] = e / s;
    }
}

// ---------------- launch ----------------
extern "C" void kernel_launch(void* const* d_in, const int* in_sizes, int n_in,
                              void* d_out, int out_size) {
    const float* features = (const float*)d_in[0];
    const int*   eidx     = (const int*)  d_in[1];
    const float* ew       = (const float*)d_in[2];
    const float* w1       = (const float*)d_in[3];
    const float* b1       = (const float*)d_in[4];
    const float* gin_w1   = (const float*)d_in[5];
    const float* gin_b1   = (const float*)d_in[6];
    const float* gin_w2   = (const float*)d_in[7];
    const float* gin_b2   = (const float*)d_in[8];
    const float* gru_wih  = (const float*)d_in[9];
    const float* gru_whh  = (const float*)d_in[10];
    const float* gru_bih  = (const float*)d_in[11];
    const float* gru_bhh  = (const float*)d_in[12];
    const float* head_w1  = (const float*)d_in[13];
    const float* head_b1  = (const float*)d_in[14];
    const float* hw2_0    = (const float*)d_in[15];
    const float* hb2_0    = (const float*)d_in[16];
    const float* hw2_1    = (const float*)d_in[17];
    const float* hb2_1    = (const float*)d_in[18];
    const float* hw2_2    = (const float*)d_in[19];
    const float* hb2_2    = (const float*)d_in[20];

    float* out = (float*)d_out;

    float *p_x, *p_agg, *p_h, *p_gi, *p_gh, *p_csr_w;
    int *p_rowptr, *p_cursor, *p_bsum, *p_boff, *p_csr_src;
    cudaGetSymbolAddress((void**)&p_x,      g_x);
    cudaGetSymbolAddress((void**)&p_agg,    g_agg);
    cudaGetSymbolAddress((void**)&p_h,      g_h);
    cudaGetSymbolAddress((void**)&p_gi,     g_gi);
    cudaGetSymbolAddress((void**)&p_gh,     g_gh);
    cudaGetSymbolAddress((void**)&p_rowptr, g_rowptr);
    cudaGetSymbolAddress((void**)&p_cursor, g_cursor);
    cudaGetSymbolAddress((void**)&p_bsum,   g_blocksum);
    cudaGetSymbolAddress((void**)&p_boff,   g_blockoff);
    cudaGetSymbolAddress((void**)&p_csr_src,g_csr_src);
    cudaGetSymbolAddress((void**)&p_csr_w,  g_csr_w);

    const int M = NNODES;
    const int E = NEDGES;
    const int gemm_gx = (M + 127) / 128;                   // 782
    const int warp_blocks = (M * 32 + 255) / 256;
    const int elem_blocks = (M * HDIM + 255) / 256;
    const int edge_blocks = (E + 255) / 256;
    const int node_blocks = (M + 255) / 256;
    const int NH = M * HDIM;

    const int* e_dst = eidx;
    const int* e_src = eidx + E;

    const size_t o_log0 = 0;
    const size_t o_log1 = (size_t)M * 2;
    const size_t o_log2 = (size_t)M * 8;
    const size_t o_soft = (size_t)M * 29;

    // ---- build CSR ----
    k_deg_zero<<<node_blocks, 256>>>(p_cursor, M);
    k_hist<<<edge_blocks, 256>>>(e_dst, p_cursor, E);
    k_scan_local<<<NSCANB, SCAN_B>>>(p_cursor, p_rowptr, p_bsum, M);
    k_scan_block<<<1, 32>>>(p_bsum, p_boff, p_rowptr, NSCANB, M);
    k_scan_add<<<node_blocks, 256>>>(p_rowptr, p_cursor, p_boff, M);
    k_scatter<<<edge_blocks, 256>>>(e_dst, e_src, ew, p_cursor, p_csr_src, p_csr_w, E);

    // x = relu(features @ w1^T + b1)
    k_gemm_t<true><<<dim3(gemm_gx, 1), 256>>>(features, w1, b1, p_x, M, HDIM);

    for (int i = 0; i < NL; i++) {
        k_spmm_csr<<<warp_blocks, 256>>>(p_rowptr, p_csr_src, p_csr_w, p_x, p_agg, M);

        k_gemm_t<false><<<dim3(gemm_gx, 3), 256>>>(p_agg, gru_wih + (size_t)i * 384 * HDIM,
                                                   gru_bih + (size_t)i * 384, p_gi, M, 384);
        k_gemm_t<false><<<dim3(gemm_gx, 3), 256>>>(p_x,   gru_whh + (size_t)i * 384 * HDIM,
                                                   gru_bhh + (size_t)i * 384, p_gh, M, 384);
        k_gru<<<elem_blocks, 256>>>(p_gi, p_gh, p_x, p_h, NH);

        k_gemm_t<true><<<dim3(gemm_gx, 1), 256>>>(p_h,   gin_w1 + (size_t)i * HDIM * HDIM,
                                                  gin_b1 + (size_t)i * HDIM, p_agg, M, HDIM);
        k_gemm_t<true><<<dim3(gemm_gx, 1), 256>>>(p_agg, gin_w2 + (size_t)i * HDIM * HDIM,
                                                  gin_b2 + (size_t)i * HDIM, p_x, M, HDIM);
        k_norm<<<warp_blocks, 256>>>(p_x, M);

        k_gemm_t<true><<<dim3(gemm_gx, 1), 256>>>(p_x, head_w1 + (size_t)i * HDIM * HDIM,
                                                  head_b1 + (size_t)i * HDIM, p_h, M, HDIM);
        if (i == 0)
            k_head<2><<<warp_blocks, 256>>>(p_h, hw2_0, hb2_0,
                                            out + o_log0, out + o_soft + 0, M);
        else if (i == 1)
            k_head<6><<<warp_blocks, 256>>>(p_h, hw2_1, hb2_1,
                                            out + o_log1, out + o_soft + (size_t)M * 2, M);
        else
            k_head<21><<<warp_blocks, 256>>>(p_h, hw2_2, hb2_2,
                                             out + o_log2, out + o_soft + (size_t)M * 8, M);
    }
}

// round 6
// speedup vs baseline: 4.2652x; 1.2414x over previous
#include <cuda_runtime.h>
#include <cuda_bf16.h>
#include <math.h>

#define NNODES 100000
#define NEDGES 1600000
#define HDIM   128
#define NL     3
#define SCAN_B 512
#define NSCANB ((NNODES + SCAN_B - 1) / SCAN_B)   // 196

// ---------------- scratch (no allocations allowed) ----------------
__device__ float g_x  [(size_t)NNODES * HDIM];
__device__ float g_agg[(size_t)NNODES * HDIM];
__device__ float g_h  [(size_t)NNODES * HDIM];
__device__ float g_gi [(size_t)NNODES * 3 * HDIM];
__device__ float g_gh [(size_t)NNODES * 3 * HDIM];
// CSR scratch
__device__ int   g_rowptr[NNODES + 1];
__device__ int   g_cursor[NNODES];
__device__ int   g_blocksum[NSCANB];
__device__ int   g_blockoff[NSCANB];
__device__ int   g_csr_src[NEDGES];
__device__ float g_csr_w  [NEDGES];

// ---------------- CSR build ----------------
__global__ void k_deg_zero(int* deg, int n) {
    int i = blockIdx.x * blockDim.x + threadIdx.x;
    if (i < n) deg[i] = 0;
}

__global__ void k_hist(const int* __restrict__ dst, int* __restrict__ deg, int E) {
    int i = blockIdx.x * blockDim.x + threadIdx.x;
    if (i < E) atomicAdd(&deg[dst[i]], 1);
}

__global__ __launch_bounds__(SCAN_B) void k_scan_local(const int* __restrict__ deg,
                                                       int* __restrict__ rowptr,
                                                       int* __restrict__ blocksum, int n) {
    __shared__ int s[SCAN_B];
    int tid = threadIdx.x;
    int i = blockIdx.x * SCAN_B + tid;
    int v = (i < n) ? deg[i] : 0;
    s[tid] = v;
    __syncthreads();
    for (int off = 1; off < SCAN_B; off <<= 1) {
        int t = (tid >= off) ? s[tid - off] : 0;
        __syncthreads();
        s[tid] += t;
        __syncthreads();
    }
    if (i < n) rowptr[i] = s[tid] - v;
    if (tid == SCAN_B - 1) blocksum[blockIdx.x] = s[tid];
}

__global__ void k_scan_block(const int* __restrict__ blocksum, int* __restrict__ blockoff,
                             int* __restrict__ rowptr, int nblk, int n) {
    if (threadIdx.x == 0 && blockIdx.x == 0) {
        int acc = 0;
        for (int b = 0; b < nblk; b++) { blockoff[b] = acc; acc += blocksum[b]; }
        rowptr[n] = acc;
    }
}

__global__ void k_scan_add(int* __restrict__ rowptr, int* __restrict__ cursor,
                           const int* __restrict__ blockoff, int n) {
    int i = blockIdx.x * blockDim.x + threadIdx.x;
    if (i < n) {
        int v = rowptr[i] + blockoff[i / SCAN_B];
        rowptr[i] = v;
        cursor[i] = v;
    }
}

__global__ void k_scatter(const int* __restrict__ dst, const int* __restrict__ src,
                          const float* __restrict__ ew, int* __restrict__ cursor,
                          int* __restrict__ csr_src, float* __restrict__ csr_w, int E) {
    int i = blockIdx.x * blockDim.x + threadIdx.x;
    if (i < E) {
        int pos = atomicAdd(&cursor[dst[i]], 1);
        csr_src[pos] = src[i];
        csr_w[pos] = ew[i];
    }
}

// ---------------- SpMM (CSR, warp per node, no atomics) ----------------
__global__ __launch_bounds__(256) void k_spmm_csr(
    const int* __restrict__ rowptr, const int* __restrict__ csr_src,
    const float* __restrict__ csr_w, const float* __restrict__ x,
    float* __restrict__ agg, int n) {
    int row = (blockIdx.x * blockDim.x + threadIdx.x) >> 5;
    int lane = threadIdx.x & 31;
    if (row >= n) return;
    int e = rowptr[row];
    int end = rowptr[row + 1];
    const float4* x4 = reinterpret_cast<const float4*>(x);
    float4 a0 = make_float4(0.f, 0.f, 0.f, 0.f);
    float4 a1 = make_float4(0.f, 0.f, 0.f, 0.f);
    for (; e + 1 < end; e += 2) {
        int s0 = csr_src[e];
        int s1 = csr_src[e + 1];
        float w0 = csr_w[e];
        float w1 = csr_w[e + 1];
        float4 v0 = x4[(size_t)s0 * 32 + lane];
        float4 v1 = x4[(size_t)s1 * 32 + lane];
        a0.x = fmaf(w0, v0.x, a0.x); a0.y = fmaf(w0, v0.y, a0.y);
        a0.z = fmaf(w0, v0.z, a0.z); a0.w = fmaf(w0, v0.w, a0.w);
        a1.x = fmaf(w1, v1.x, a1.x); a1.y = fmaf(w1, v1.y, a1.y);
        a1.z = fmaf(w1, v1.z, a1.z); a1.w = fmaf(w1, v1.w, a1.w);
    }
    if (e < end) {
        int s0 = csr_src[e];
        float w0 = csr_w[e];
        float4 v0 = x4[(size_t)s0 * 32 + lane];
        a0.x = fmaf(w0, v0.x, a0.x); a0.y = fmaf(w0, v0.y, a0.y);
        a0.z = fmaf(w0, v0.z, a0.z); a0.w = fmaf(w0, v0.w, a0.w);
    }
    a0.x += a1.x; a0.y += a1.y; a0.z += a1.z; a0.w += a1.w;
    reinterpret_cast<float4*>(agg)[(size_t)row * 32 + lane] = a0;
}

// ---------------- BF16 tensor-core GEMM ----------------
// C[M,Ncol] = act(A[M,128] @ W[Ncol,128]^T + bias)
// tile 128x128, full K=128 resident in smem as bf16 pairs
#define KPAIRS 64            // 128 k / 2 per unsigned
#define KSTRIDE 68           // row stride in unsigned (pad 4)

__device__ __forceinline__ unsigned pack_bf16(float a, float b) {
    __nv_bfloat162 t = __floats2bfloat162_rn(a, b);
    return *reinterpret_cast<unsigned*>(&t);
}

__device__ __forceinline__ void mma_bf16(float* d, const unsigned* a, const unsigned* b) {
    asm volatile(
        "mma.sync.aligned.m16n8k16.row.col.f32.bf16.bf16.f32 "
        "{%0,%1,%2,%3}, {%4,%5,%6,%7}, {%8,%9}, {%0,%1,%2,%3};\n"
        : "+f"(d[0]), "+f"(d[1]), "+f"(d[2]), "+f"(d[3])
        : "r"(a[0]), "r"(a[1]), "r"(a[2]), "r"(a[3]), "r"(b[0]), "r"(b[1]));
}

template <bool RELU>
__global__ __launch_bounds__(256) void k_gemm_b(
    const float* __restrict__ A, const float* __restrict__ W,
    const float* __restrict__ bias, float* __restrict__ C,
    int M, int Ncol)
{
    extern __shared__ unsigned smem_u[];
    unsigned* As = smem_u;                       // [128][KSTRIDE]
    unsigned* Ws = smem_u + 128 * KSTRIDE;       // [128][KSTRIDE]

    const int tid = threadIdx.x;
    const int wid = tid >> 5;
    const int lane = tid & 31;
    const int g = lane >> 2;          // 0..7
    const int t4 = lane & 3;          // 0..3
    const int wm = wid & 3;           // warp m-tile (32 rows)
    const int wn = wid >> 2;          // warp n-tile (64 cols)
    const int m0 = blockIdx.x * 128;
    const int n0 = blockIdx.y * 128;

    // ---- load + convert: linear float4 index for full coalescing ----
    // each row = 32 float4 (128 floats). 128 rows * 32 = 4096 float4 per matrix.
#pragma unroll
    for (int p = 0; p < 16; p++) {
        int F = p * 256 + tid;
        int row = F >> 5;             // F / 32
        int c = F & 31;               // float4 index within row (cols c*4..c*4+3)
        int gm = m0 + row;
        float4 va = make_float4(0.f, 0.f, 0.f, 0.f);
        if (gm < M) va = *reinterpret_cast<const float4*>(A + (size_t)gm * HDIM + c * 4);
        As[row * KSTRIDE + c * 2 + 0] = pack_bf16(va.x, va.y);
        As[row * KSTRIDE + c * 2 + 1] = pack_bf16(va.z, va.w);
        float4 vb = *reinterpret_cast<const float4*>(W + (size_t)(n0 + row) * HDIM + c * 4);
        Ws[row * KSTRIDE + c * 2 + 0] = pack_bf16(vb.x, vb.y);
        Ws[row * KSTRIDE + c * 2 + 1] = pack_bf16(vb.z, vb.w);
    }
    __syncthreads();

    float acc[2][8][4];
#pragma unroll
    for (int i = 0; i < 2; i++)
#pragma unroll
        for (int j = 0; j < 8; j++)
#pragma unroll
            for (int r = 0; r < 4; r++) acc[i][j][r] = 0.f;

#pragma unroll
    for (int ks = 0; ks < 8; ks++) {           // 8 k16 steps
        int kb = ks * 8;                        // pair offset
        unsigned af[2][4];
#pragma unroll
        for (int i = 0; i < 2; i++) {
            int rb = wm * 32 + i * 16;
            af[i][0] = As[(rb + g) * KSTRIDE + kb + t4];
            af[i][1] = As[(rb + 8 + g) * KSTRIDE + kb + t4];
            af[i][2] = As[(rb + g) * KSTRIDE + kb + t4 + 4];
            af[i][3] = As[(rb + 8 + g) * KSTRIDE + kb + t4 + 4];
        }
        unsigned bf[8][2];
#pragma unroll
        for (int j = 0; j < 8; j++) {
            int nb = wn * 64 + j * 8;
            bf[j][0] = Ws[(nb + g) * KSTRIDE + kb + t4];
            bf[j][1] = Ws[(nb + g) * KSTRIDE + kb + t4 + 4];
        }
#pragma unroll
        for (int i = 0; i < 2; i++)
#pragma unroll
            for (int j = 0; j < 8; j++)
                mma_bf16(acc[i][j], af[i], bf[j]);
    }

    // ---- epilogue ----
#pragma unroll
    for (int i = 0; i < 2; i++) {
        int row_lo = m0 + wm * 32 + i * 16 + g;
        int row_hi = row_lo + 8;
#pragma unroll
        for (int j = 0; j < 8; j++) {
            int col = n0 + wn * 64 + j * 8 + 2 * t4;
            float b0 = bias[col];
            float b1 = bias[col + 1];
            if (row_lo < M) {
                float v0 = acc[i][j][0] + b0;
                float v1 = acc[i][j][1] + b1;
                if (RELU) { v0 = fmaxf(v0, 0.f); v1 = fmaxf(v1, 0.f); }
                *reinterpret_cast<float2*>(C + (size_t)row_lo * Ncol + col) = make_float2(v0, v1);
            }
            if (row_hi < M) {
                float v2 = acc[i][j][2] + b0;
                float v3 = acc[i][j][3] + b1;
                if (RELU) { v2 = fmaxf(v2, 0.f); v3 = fmaxf(v3, 0.f); }
                *reinterpret_cast<float2*>(C + (size_t)row_hi * Ncol + col) = make_float2(v2, v3);
            }
        }
    }
}

#define GEMM_SMEM (2 * 128 * KSTRIDE * 4)

// ---------------- GRU elementwise ----------------
__device__ __forceinline__ float sigm(float x) { return 1.f / (1.f + expf(-x)); }

__global__ void k_gru(const float* __restrict__ gi, const float* __restrict__ gh,
                      const float* __restrict__ li, float* __restrict__ h, int total) {
    int i = blockIdx.x * blockDim.x + threadIdx.x;
    if (i >= total) return;
    int n = i >> 7;
    int j = i & 127;
    const float* a = gi + (size_t)n * 384;
    const float* b = gh + (size_t)n * 384;
    float r = sigm(a[j] + b[j]);
    float z = sigm(a[128 + j] + b[128 + j]);
    float nn = tanhf(a[256 + j] + r * b[256 + j]);
    float l = li[i];
    h[i] = (1.f - z) * nn + z * l;
}

// ---------------- row norm ----------------
__global__ void k_norm(float* __restrict__ x, int M) {
    int row = (blockIdx.x * blockDim.x + threadIdx.x) >> 5;
    int lane = threadIdx.x & 31;
    if (row >= M) return;
    float4* p = reinterpret_cast<float4*>(x + (size_t)row * HDIM);
    float4 v = p[lane];
    float s = v.x * v.x + v.y * v.y + v.z * v.z + v.w * v.w;
#pragma unroll
    for (int o = 16; o; o >>= 1) s += __shfl_xor_sync(0xffffffffu, s, o);
    float inv = rsqrtf(1.f + s);
    v.x *= inv; v.y *= inv; v.z *= inv; v.w *= inv;
    p[lane] = v;
}

// ---------------- head ----------------
template <int C>
__global__ void k_head(const float* __restrict__ t, const float* __restrict__ w2,
                       const float* __restrict__ b2,
                       float* __restrict__ out_log, float* __restrict__ out_soft, int M) {
    int node = (blockIdx.x * blockDim.x + threadIdx.x) >> 5;
    int lane = threadIdx.x & 31;
    if (node >= M) return;
    float4 v = reinterpret_cast<const float4*>(t + (size_t)node * HDIM)[lane];
    float myval = 0.f;
#pragma unroll
    for (int c = 0; c < C; c++) {
        float4 w = reinterpret_cast<const float4*>(w2 + (size_t)c * HDIM)[lane];
        float p = v.x * w.x + v.y * w.y + v.z * w.z + v.w * w.w;
#pragma unroll
        for (int o = 16; o; o >>= 1) p += __shfl_xor_sync(0xffffffffu, p, o);
        if (lane == c) myval = p + b2[c];
    }
    float m = (lane < C) ? myval : -INFINITY;
#pragma unroll
    for (int o = 16; o; o >>= 1) m = fmaxf(m, __shfl_xor_sync(0xffffffffu, m, o));
    float e = (lane < C) ? expf(myval - m) : 0.f;
    float s = e;
#pragma unroll
    for (int o = 16; o; o >>= 1) s += __shfl_xor_sync(0xffffffffu, s, o);
    if (lane < C) {
        out_log [(size_t)node * C + lane] = myval - m - logf(s);
        out_soft[(size_t)node * C + lane] = e / s;
    }
}

// ---------------- launch ----------------
extern "C" void kernel_launch(void* const* d_in, const int* in_sizes, int n_in,
                              void* d_out, int out_size) {
    const float* features = (const float*)d_in[0];
    const int*   eidx     = (const int*)  d_in[1];
    const float* ew       = (const float*)d_in[2];
    const float* w1       = (const float*)d_in[3];
    const float* b1       = (const float*)d_in[4];
    const float* gin_w1   = (const float*)d_in[5];
    const float* gin_b1   = (const float*)d_in[6];
    const float* gin_w2   = (const float*)d_in[7];
    const float* gin_b2   = (const float*)d_in[8];
    const float* gru_wih  = (const float*)d_in[9];
    const float* gru_whh  = (const float*)d_in[10];
    const float* gru_bih  = (const float*)d_in[11];
    const float* gru_bhh  = (const float*)d_in[12];
    const float* head_w1  = (const float*)d_in[13];
    const float* head_b1  = (const float*)d_in[14];
    const float* hw2_0    = (const float*)d_in[15];
    const float* hb2_0    = (const float*)d_in[16];
    const float* hw2_1    = (const float*)d_in[17];
    const float* hb2_1    = (const float*)d_in[18];
    const float* hw2_2    = (const float*)d_in[19];
    const float* hb2_2    = (const float*)d_in[20];

    float* out = (float*)d_out;

    float *p_x, *p_agg, *p_h, *p_gi, *p_gh, *p_csr_w;
    int *p_rowptr, *p_cursor, *p_bsum, *p_boff, *p_csr_src;
    cudaGetSymbolAddress((void**)&p_x,      g_x);
    cudaGetSymbolAddress((void**)&p_agg,    g_agg);
    cudaGetSymbolAddress((void**)&p_h,      g_h);
    cudaGetSymbolAddress((void**)&p_gi,     g_gi);
    cudaGetSymbolAddress((void**)&p_gh,     g_gh);
    cudaGetSymbolAddress((void**)&p_rowptr, g_rowptr);
    cudaGetSymbolAddress((void**)&p_cursor, g_cursor);
    cudaGetSymbolAddress((void**)&p_bsum,   g_blocksum);
    cudaGetSymbolAddress((void**)&p_boff,   g_blockoff);
    cudaGetSymbolAddress((void**)&p_csr_src,g_csr_src);
    cudaGetSymbolAddress((void**)&p_csr_w,  g_csr_w);

    cudaFuncSetAttribute(k_gemm_b<true>,  cudaFuncAttributeMaxDynamicSharedMemorySize, GEMM_SMEM);
    cudaFuncSetAttribute(k_gemm_b<false>, cudaFuncAttributeMaxDynamicSharedMemorySize, GEMM_SMEM);

    const int M = NNODES;
    const int E = NEDGES;
    const int gemm_gx = (M + 127) / 128;                   // 782
    const int warp_blocks = (M * 32 + 255) / 256;
    const int elem_blocks = (M * HDIM + 255) / 256;
    const int edge_blocks = (E + 255) / 256;
    const int node_blocks = (M + 255) / 256;
    const int NH = M * HDIM;

    const int* e_dst = eidx;
    const int* e_src = eidx + E;

    const size_t o_log0 = 0;
    const size_t o_log1 = (size_t)M * 2;
    const size_t o_log2 = (size_t)M * 8;
    const size_t o_soft = (size_t)M * 29;

    // ---- build CSR ----
    k_deg_zero<<<node_blocks, 256>>>(p_cursor, M);
    k_hist<<<edge_blocks, 256>>>(e_dst, p_cursor, E);
    k_scan_local<<<NSCANB, SCAN_B>>>(p_cursor, p_rowptr, p_bsum, M);
    k_scan_block<<<1, 32>>>(p_bsum, p_boff, p_rowptr, NSCANB, M);
    k_scan_add<<<node_blocks, 256>>>(p_rowptr, p_cursor, p_boff, M);
    k_scatter<<<edge_blocks, 256>>>(e_dst, e_src, ew, p_cursor, p_csr_src, p_csr_w, E);

    // x = relu(features @ w1^T + b1)
    k_gemm_b<true><<<dim3(gemm_gx, 1), 256, GEMM_SMEM>>>(features, w1, b1, p_x, M, HDIM);

    for (int i = 0; i < NL; i++) {
        k_spmm_csr<<<warp_blocks, 256>>>(p_rowptr, p_csr_src, p_csr_w, p_x, p_agg, M);

        k_gemm_b<false><<<dim3(gemm_gx, 3), 256, GEMM_SMEM>>>(p_agg, gru_wih + (size_t)i * 384 * HDIM,
                                                              gru_bih + (size_t)i * 384, p_gi, M, 384);
        k_gemm_b<false><<<dim3(gemm_gx, 3), 256, GEMM_SMEM>>>(p_x,   gru_whh + (size_t)i * 384 * HDIM,
                                                              gru_bhh + (size_t)i * 384, p_gh, M, 384);
        k_gru<<<elem_blocks, 256>>>(p_gi, p_gh, p_x, p_h, NH);

        k_gemm_b<true><<<dim3(gemm_gx, 1), 256, GEMM_SMEM>>>(p_h,   gin_w1 + (size_t)i * HDIM * HDIM,
                                                             gin_b1 + (size_t)i * HDIM, p_agg, M, HDIM);
        k_gemm_b<true><<<dim3(gemm_gx, 1), 256, GEMM_SMEM>>>(p_agg, gin_w2 + (size_t)i * HDIM * HDIM,
                                                             gin_b2 + (size_t)i * HDIM, p_x, M, HDIM);
        k_norm<<<warp_blocks, 256>>>(p_x, M);

        k_gemm_b<true><<<dim3(gemm_gx, 1), 256, GEMM_SMEM>>>(p_x, head_w1 + (size_t)i * HDIM * HDIM,
                                                             head_b1 + (size_t)i * HDIM, p_h, M, HDIM);
        if (i == 0)
            k_head<2><<<warp_blocks, 256>>>(p_h, hw2_0, hb2_0,
                                            out + o_log0, out + o_soft + 0, M);
        else if (i == 1)
            k_head<6><<<warp_blocks, 256>>>(p_h, hw2_1, hb2_1,
                                            out + o_log1, out + o_soft + (size_t)M * 2, M);
        else
            k_head<21><<<warp_blocks, 256>>>(p_h, hw2_2, hb2_2,
                                             out + o_log2, out + o_soft + (size_t)M * 8, M);
    }
}

// round 7
// speedup vs baseline: 4.9907x; 1.1701x over previous
#include <cuda_runtime.h>
#include <cuda_bf16.h>
#include <math.h>

#define NNODES 100000
#define NEDGES 1600000
#define HDIM   128
#define NL     3
#define SCAN_B 512
#define NSCANB ((NNODES + SCAN_B - 1) / SCAN_B)   // 196

#define KSTRIDE 68                 // smem row stride in u32 (64 bf16-pairs + pad 4)
#define TILE_U32 (128 * KSTRIDE)   // one 128x128 bf16 tile

// ---------------- scratch (no allocations allowed) ----------------
__device__ float g_x  [(size_t)NNODES * HDIM];
__device__ float g_agg[(size_t)NNODES * HDIM];
__device__ float g_h  [(size_t)NNODES * HDIM];
// CSR scratch
__device__ int   g_rowptr[NNODES + 1];
__device__ int   g_cursor[NNODES];
__device__ int   g_blocksum[NSCANB];
__device__ int   g_blockoff[NSCANB];
__device__ int   g_csr_src[NEDGES];
__device__ float g_csr_w  [NEDGES];

// ---------------- CSR build ----------------
__global__ void k_deg_zero(int* deg, int n) {
    int i = blockIdx.x * blockDim.x + threadIdx.x;
    if (i < n) deg[i] = 0;
}

__global__ void k_hist(const int* __restrict__ dst, int* __restrict__ deg, int E) {
    int i = blockIdx.x * blockDim.x + threadIdx.x;
    if (i < E) atomicAdd(&deg[dst[i]], 1);
}

__global__ __launch_bounds__(SCAN_B) void k_scan_local(const int* __restrict__ deg,
                                                       int* __restrict__ rowptr,
                                                       int* __restrict__ blocksum, int n) {
    __shared__ int s[SCAN_B];
    int tid = threadIdx.x;
    int i = blockIdx.x * SCAN_B + tid;
    int v = (i < n) ? deg[i] : 0;
    s[tid] = v;
    __syncthreads();
    for (int off = 1; off < SCAN_B; off <<= 1) {
        int t = (tid >= off) ? s[tid - off] : 0;
        __syncthreads();
        s[tid] += t;
        __syncthreads();
    }
    if (i < n) rowptr[i] = s[tid] - v;
    if (tid == SCAN_B - 1) blocksum[blockIdx.x] = s[tid];
}

__global__ void k_scan_block(const int* __restrict__ blocksum, int* __restrict__ blockoff,
                             int* __restrict__ rowptr, int nblk, int n) {
    if (threadIdx.x == 0 && blockIdx.x == 0) {
        int acc = 0;
        for (int b = 0; b < nblk; b++) { blockoff[b] = acc; acc += blocksum[b]; }
        rowptr[n] = acc;
    }
}

__global__ void k_scan_add(int* __restrict__ rowptr, int* __restrict__ cursor,
                           const int* __restrict__ blockoff, int n) {
    int i = blockIdx.x * blockDim.x + threadIdx.x;
    if (i < n) {
        int v = rowptr[i] + blockoff[i / SCAN_B];
        rowptr[i] = v;
        cursor[i] = v;
    }
}

__global__ void k_scatter(const int* __restrict__ dst, const int* __restrict__ src,
                          const float* __restrict__ ew, int* __restrict__ cursor,
                          int* __restrict__ csr_src, float* __restrict__ csr_w, int E) {
    int i = blockIdx.x * blockDim.x + threadIdx.x;
    if (i < E) {
        int pos = atomicAdd(&cursor[dst[i]], 1);
        csr_src[pos] = src[i];
        csr_w[pos] = ew[i];
    }
}

// ---------------- SpMM (CSR, warp per node, no atomics) ----------------
__global__ __launch_bounds__(256) void k_spmm_csr(
    const int* __restrict__ rowptr, const int* __restrict__ csr_src,
    const float* __restrict__ csr_w, const float* __restrict__ x,
    float* __restrict__ agg, int n) {
    int row = (blockIdx.x * blockDim.x + threadIdx.x) >> 5;
    int lane = threadIdx.x & 31;
    if (row >= n) return;
    int e = rowptr[row];
    int end = rowptr[row + 1];
    const float4* x4 = reinterpret_cast<const float4*>(x);
    float4 a0 = make_float4(0.f, 0.f, 0.f, 0.f);
    float4 a1 = make_float4(0.f, 0.f, 0.f, 0.f);
    for (; e + 1 < end; e += 2) {
        int s0 = csr_src[e];
        int s1 = csr_src[e + 1];
        float w0 = csr_w[e];
        float w1 = csr_w[e + 1];
        float4 v0 = x4[(size_t)s0 * 32 + lane];
        float4 v1 = x4[(size_t)s1 * 32 + lane];
        a0.x = fmaf(w0, v0.x, a0.x); a0.y = fmaf(w0, v0.y, a0.y);
        a0.z = fmaf(w0, v0.z, a0.z); a0.w = fmaf(w0, v0.w, a0.w);
        a1.x = fmaf(w1, v1.x, a1.x); a1.y = fmaf(w1, v1.y, a1.y);
        a1.z = fmaf(w1, v1.z, a1.z); a1.w = fmaf(w1, v1.w, a1.w);
    }
    if (e < end) {
        int s0 = csr_src[e];
        float w0 = csr_w[e];
        float4 v0 = x4[(size_t)s0 * 32 + lane];
        a0.x = fmaf(w0, v0.x, a0.x); a0.y = fmaf(w0, v0.y, a0.y);
        a0.z = fmaf(w0, v0.z, a0.z); a0.w = fmaf(w0, v0.w, a0.w);
    }
    a0.x += a1.x; a0.y += a1.y; a0.z += a1.z; a0.w += a1.w;
    reinterpret_cast<float4*>(agg)[(size_t)row * 32 + lane] = a0;
}

// ---------------- bf16 mma helpers ----------------
__device__ __forceinline__ unsigned pack_bf16(float a, float b) {
    __nv_bfloat162 t = __floats2bfloat162_rn(a, b);
    return *reinterpret_cast<unsigned*>(&t);
}

__device__ __forceinline__ void mma_bf16(float* d, const unsigned* a, const unsigned* b) {
    asm volatile(
        "mma.sync.aligned.m16n8k16.row.col.f32.bf16.bf16.f32 "
        "{%0,%1,%2,%3}, {%4,%5,%6,%7}, {%8,%9}, {%0,%1,%2,%3};\n"
        : "+f"(d[0]), "+f"(d[1]), "+f"(d[2]), "+f"(d[3])
        : "r"(a[0]), "r"(a[1]), "r"(a[2]), "r"(a[3]), "r"(b[0]), "r"(b[1]));
}

// accumulate full 128x128x128: acc += A_tile @ W_tile^T for this warp's fragments
__device__ __forceinline__ void gemm128(const unsigned* __restrict__ As,
                                        const unsigned* __restrict__ Ws,
                                        float acc[2][8][4],
                                        int wm, int wn, int g, int t4) {
#pragma unroll
    for (int ks = 0; ks < 8; ks++) {
        int kb = ks * 8;
        unsigned af[2][4];
#pragma unroll
        for (int i = 0; i < 2; i++) {
            int rb = wm * 32 + i * 16;
            af[i][0] = As[(rb + g) * KSTRIDE + kb + t4];
            af[i][1] = As[(rb + 8 + g) * KSTRIDE + kb + t4];
            af[i][2] = As[(rb + g) * KSTRIDE + kb + t4 + 4];
            af[i][3] = As[(rb + 8 + g) * KSTRIDE + kb + t4 + 4];
        }
        unsigned bf[8][2];
#pragma unroll
        for (int j = 0; j < 8; j++) {
            int nb = wn * 64 + j * 8;
            bf[j][0] = Ws[(nb + g) * KSTRIDE + kb + t4];
            bf[j][1] = Ws[(nb + g) * KSTRIDE + kb + t4 + 4];
        }
#pragma unroll
        for (int i = 0; i < 2; i++)
#pragma unroll
            for (int j = 0; j < 8; j++)
                mma_bf16(acc[i][j], af[i], bf[j]);
    }
}

__device__ __forceinline__ void zero_acc(float acc[2][8][4]) {
#pragma unroll
    for (int i = 0; i < 2; i++)
#pragma unroll
        for (int j = 0; j < 8; j++)
#pragma unroll
            for (int r = 0; r < 4; r++) acc[i][j][r] = 0.f;
}

// load 128x128 f32 tile -> bf16 smem, rows beyond M zero-filled
__device__ __forceinline__ void load_tile_g(unsigned* dst, const float* __restrict__ src,
                                            int row0, int M, int tid) {
#pragma unroll
    for (int p = 0; p < 16; p++) {
        int F = p * 256 + tid;
        int row = F >> 5, c = F & 31;
        float4 v = make_float4(0.f, 0.f, 0.f, 0.f);
        if (row0 + row < M) v = *reinterpret_cast<const float4*>(src + (size_t)(row0 + row) * HDIM + c * 4);
        dst[row * KSTRIDE + c * 2 + 0] = pack_bf16(v.x, v.y);
        dst[row * KSTRIDE + c * 2 + 1] = pack_bf16(v.z, v.w);
    }
}

// load 128x128 f32 weights -> bf16 smem (always full)
__device__ __forceinline__ void load_w128(unsigned* dst, const float* __restrict__ src, int tid) {
#pragma unroll
    for (int p = 0; p < 16; p++) {
        int F = p * 256 + tid;
        int row = F >> 5, c = F & 31;
        float4 v = *reinterpret_cast<const float4*>(src + (size_t)row * HDIM + c * 4);
        dst[row * KSTRIDE + c * 2 + 0] = pack_bf16(v.x, v.y);
        dst[row * KSTRIDE + c * 2 + 1] = pack_bf16(v.z, v.w);
    }
}

__device__ __forceinline__ float sigm(float x) { return 1.f / (1.f + expf(-x)); }

// ---------------- standalone GEMM (mlp1 only) ----------------
template <bool RELU>
__global__ __launch_bounds__(256) void k_gemm_b(
    const float* __restrict__ A, const float* __restrict__ W,
    const float* __restrict__ bias, float* __restrict__ C,
    int M, int Ncol)
{
    extern __shared__ unsigned smem_u[];
    unsigned* As = smem_u;
    unsigned* Ws = smem_u + TILE_U32;

    const int tid = threadIdx.x;
    const int wid = tid >> 5;
    const int lane = tid & 31;
    const int g = lane >> 2;
    const int t4 = lane & 3;
    const int wm = wid & 3;
    const int wn = wid >> 2;
    const int m0 = blockIdx.x * 128;
    const int n0 = blockIdx.y * 128;

    load_tile_g(As, A, m0, M, tid);
    load_w128(Ws, W + (size_t)n0 * HDIM, tid);
    __syncthreads();

    float acc[2][8][4];
    zero_acc(acc);
    gemm128(As, Ws, acc, wm, wn, g, t4);

#pragma unroll
    for (int i = 0; i < 2; i++) {
        int row_lo = m0 + wm * 32 + i * 16 + g;
        int row_hi = row_lo + 8;
#pragma unroll
        for (int j = 0; j < 8; j++) {
            int col = n0 + wn * 64 + j * 8 + 2 * t4;
            float b0 = bias[col];
            float b1 = bias[col + 1];
            if (row_lo < M) {
                float v0 = acc[i][j][0] + b0;
                float v1 = acc[i][j][1] + b1;
                if (RELU) { v0 = fmaxf(v0, 0.f); v1 = fmaxf(v1, 0.f); }
                *reinterpret_cast<float2*>(C + (size_t)row_lo * Ncol + col) = make_float2(v0, v1);
            }
            if (row_hi < M) {
                float v2 = acc[i][j][2] + b0;
                float v3 = acc[i][j][3] + b1;
                if (RELU) { v2 = fmaxf(v2, 0.f); v3 = fmaxf(v3, 0.f); }
                *reinterpret_cast<float2*>(C + (size_t)row_hi * Ncol + col) = make_float2(v2, v3);
            }
        }
    }
}
#define GEMM_SMEM (2 * TILE_U32 * 4)

// ---------------- fused GRU: h = GRUCell(agg, x) ----------------
// per CTA: 128 nodes; agg & x tiles resident; weight chunks streamed
__global__ __launch_bounds__(256, 1) void k_gru_fused(
    const float* __restrict__ agg, const float* __restrict__ x,
    const float* __restrict__ wih, const float* __restrict__ whh,
    const float* __restrict__ bih, const float* __restrict__ bhh,
    float* __restrict__ h, int M)
{
    extern __shared__ unsigned sm[];
    unsigned* Aagg = sm;
    unsigned* Ax   = sm + TILE_U32;
    unsigned* Wb   = sm + 2 * TILE_U32;

    const int tid = threadIdx.x;
    const int wid = tid >> 5;
    const int lane = tid & 31;
    const int g = lane >> 2;
    const int t4 = lane & 3;
    const int wm = wid & 3;
    const int wn = wid >> 2;
    const int m0 = blockIdx.x * 128;

    load_tile_g(Aagg, agg, m0, M, tid);
    load_tile_g(Ax,   x,   m0, M, tid);

    float zf[2][8][4], rf[2][8][4], acc[2][8][4];

    // ---- z = sigm(gi1 + gh1 + bih1 + bhh1)  (chunk 1) ----
    zero_acc(acc);
    __syncthreads();
    load_w128(Wb, wih + 128 * HDIM, tid);
    __syncthreads();
    gemm128(Aagg, Wb, acc, wm, wn, g, t4);
    __syncthreads();
    load_w128(Wb, whh + 128 * HDIM, tid);
    __syncthreads();
    gemm128(Ax, Wb, acc, wm, wn, g, t4);
#pragma unroll
    for (int i = 0; i < 2; i++)
#pragma unroll
        for (int j = 0; j < 8; j++)
#pragma unroll
            for (int r = 0; r < 4; r++) {
                int col = wn * 64 + j * 8 + 2 * t4 + (r & 1);
                zf[i][j][r] = sigm(acc[i][j][r] + bih[128 + col] + bhh[128 + col]);
            }

    // ---- r = sigm(gi0 + gh0 + b)  (chunk 0) ----
    zero_acc(acc);
    __syncthreads();
    load_w128(Wb, wih, tid);
    __syncthreads();
    gemm128(Aagg, Wb, acc, wm, wn, g, t4);
    __syncthreads();
    load_w128(Wb, whh, tid);
    __syncthreads();
    gemm128(Ax, Wb, acc, wm, wn, g, t4);
#pragma unroll
    for (int i = 0; i < 2; i++)
#pragma unroll
        for (int j = 0; j < 8; j++)
#pragma unroll
            for (int r = 0; r < 4; r++) {
                int col = wn * 64 + j * 8 + 2 * t4 + (r & 1);
                rf[i][j][r] = sigm(acc[i][j][r] + bih[col] + bhh[col]);
            }

    // ---- n = tanh(gi2 + bih2 + r*(gh2 + bhh2))  (chunk 2) ----
    zero_acc(acc);
    __syncthreads();
    load_w128(Wb, whh + 256 * HDIM, tid);
    __syncthreads();
    gemm128(Ax, Wb, acc, wm, wn, g, t4);      // acc = gh2
#pragma unroll
    for (int i = 0; i < 2; i++)
#pragma unroll
        for (int j = 0; j < 8; j++)
#pragma unroll
            for (int r = 0; r < 4; r++) {
                int col = wn * 64 + j * 8 + 2 * t4 + (r & 1);
                acc[i][j][r] = rf[i][j][r] * (acc[i][j][r] + bhh[256 + col]);
            }
    __syncthreads();
    load_w128(Wb, wih + 256 * HDIM, tid);
    __syncthreads();
    gemm128(Aagg, Wb, acc, wm, wn, g, t4);    // acc += gi2

    // ---- h = (1-z)*n + z*x ----
#pragma unroll
    for (int i = 0; i < 2; i++) {
        int row_lo = m0 + wm * 32 + i * 16 + g;
        int row_hi = row_lo + 8;
#pragma unroll
        for (int j = 0; j < 8; j++) {
            int col = wn * 64 + j * 8 + 2 * t4;
            if (row_lo < M) {
                float2 xv = *reinterpret_cast<const float2*>(x + (size_t)row_lo * HDIM + col);
                float n0v = tanhf(acc[i][j][0] + bih[256 + col]);
                float n1v = tanhf(acc[i][j][1] + bih[256 + col + 1]);
                float h0 = (1.f - zf[i][j][0]) * n0v + zf[i][j][0] * xv.x;
                float h1 = (1.f - zf[i][j][1]) * n1v + zf[i][j][1] * xv.y;
                *reinterpret_cast<float2*>(h + (size_t)row_lo * HDIM + col) = make_float2(h0, h1);
            }
            if (row_hi < M) {
                float2 xv = *reinterpret_cast<const float2*>(x + (size_t)row_hi * HDIM + col);
                float n2v = tanhf(acc[i][j][2] + bih[256 + col]);
                float n3v = tanhf(acc[i][j][3] + bih[256 + col + 1]);
                float h2 = (1.f - zf[i][j][2]) * n2v + zf[i][j][2] * xv.x;
                float h3 = (1.f - zf[i][j][3]) * n3v + zf[i][j][3] * xv.y;
                *reinterpret_cast<float2*>(h + (size_t)row_hi * HDIM + col) = make_float2(h2, h3);
            }
        }
    }
}
#define GRU_SMEM (3 * TILE_U32 * 4)

// ---------------- fused GIN MLP + norm + head + softmax ----------------
template <int C>
__global__ __launch_bounds__(256, 1) void k_gin_head(
    const float* __restrict__ h,
    const float* __restrict__ g1, const float* __restrict__ b1v,
    const float* __restrict__ g2, const float* __restrict__ b2v,
    const float* __restrict__ hw1, const float* __restrict__ hb1,
    const float* __restrict__ w2, const float* __restrict__ bh2,
    float* __restrict__ xout, float* __restrict__ olog, float* __restrict__ osoft,
    int M)
{
    extern __shared__ unsigned sm[];
    unsigned* Ah   = sm;                       // h tile / later x tile
    unsigned* Wb   = sm + TILE_U32;            // streamed weights
    unsigned* At1  = sm + 2 * TILE_U32;        // t1 tile / later t2 tile
    unsigned* W2s  = sm + 3 * TILE_U32;        // head w2 (24 rows padded)
    float* rowsum  = reinterpret_cast<float*>(W2s + 24 * KSTRIDE);  // [128]
    float* logit   = rowsum + 128;             // [128][28]

    const int tid = threadIdx.x;
    const int wid = tid >> 5;
    const int lane = tid & 31;
    const int g = lane >> 2;
    const int t4 = lane & 3;
    const int wm = wid & 3;
    const int wn = wid >> 2;
    const int m0 = blockIdx.x * 128;

    if (tid < 128) rowsum[tid] = 0.f;
    load_tile_g(Ah, h, m0, M, tid);
    load_w128(Wb, g1, tid);
    __syncthreads();

    float acc[2][8][4];

    // ---- t1 = relu(h @ g1^T + b1) ----
    zero_acc(acc);
    gemm128(Ah, Wb, acc, wm, wn, g, t4);
#pragma unroll
    for (int i = 0; i < 2; i++) {
        int rl = wm * 32 + i * 16 + g;
#pragma unroll
        for (int j = 0; j < 8; j++) {
            int col = wn * 64 + j * 8 + 2 * t4;
            float v0 = fmaxf(acc[i][j][0] + b1v[col], 0.f);
            float v1 = fmaxf(acc[i][j][1] + b1v[col + 1], 0.f);
            float v2 = fmaxf(acc[i][j][2] + b1v[col], 0.f);
            float v3 = fmaxf(acc[i][j][3] + b1v[col + 1], 0.f);
            At1[rl * KSTRIDE + (col >> 1)] = pack_bf16(v0, v1);
            At1[(rl + 8) * KSTRIDE + (col >> 1)] = pack_bf16(v2, v3);
        }
    }
    __syncthreads();

    // ---- x = relu(t1 @ g2^T + b2), rowsum ----
    load_w128(Wb, g2, tid);
    __syncthreads();
    zero_acc(acc);
    gemm128(At1, Wb, acc, wm, wn, g, t4);
#pragma unroll
    for (int i = 0; i < 2; i++) {
        float s_lo = 0.f, s_hi = 0.f;
#pragma unroll
        for (int j = 0; j < 8; j++) {
            int col = wn * 64 + j * 8 + 2 * t4;
            acc[i][j][0] = fmaxf(acc[i][j][0] + b2v[col], 0.f);
            acc[i][j][1] = fmaxf(acc[i][j][1] + b2v[col + 1], 0.f);
            acc[i][j][2] = fmaxf(acc[i][j][2] + b2v[col], 0.f);
            acc[i][j][3] = fmaxf(acc[i][j][3] + b2v[col + 1], 0.f);
            s_lo += acc[i][j][0] * acc[i][j][0] + acc[i][j][1] * acc[i][j][1];
            s_hi += acc[i][j][2] * acc[i][j][2] + acc[i][j][3] * acc[i][j][3];
        }
        atomicAdd(&rowsum[wm * 32 + i * 16 + g], s_lo);
        atomicAdd(&rowsum[wm * 32 + i * 16 + 8 + g], s_hi);
    }
    __syncthreads();

    // ---- scale by rsqrt(1+sum), write x, repack to Ah; load hw1 + w2 ----
#pragma unroll
    for (int i = 0; i < 2; i++) {
        int rl = wm * 32 + i * 16 + g;
        float inv_lo = rsqrtf(1.f + rowsum[rl]);
        float inv_hi = rsqrtf(1.f + rowsum[rl + 8]);
        int gm_lo = m0 + rl;
        int gm_hi = gm_lo + 8;
#pragma unroll
        for (int j = 0; j < 8; j++) {
            int col = wn * 64 + j * 8 + 2 * t4;
            float v0 = acc[i][j][0] * inv_lo;
            float v1 = acc[i][j][1] * inv_lo;
            float v2 = acc[i][j][2] * inv_hi;
            float v3 = acc[i][j][3] * inv_hi;
            Ah[rl * KSTRIDE + (col >> 1)] = pack_bf16(v0, v1);
            Ah[(rl + 8) * KSTRIDE + (col >> 1)] = pack_bf16(v2, v3);
            if (gm_lo < M)
                *reinterpret_cast<float2*>(xout + (size_t)gm_lo * HDIM + col) = make_float2(v0, v1);
            if (gm_hi < M)
                *reinterpret_cast<float2*>(xout + (size_t)gm_hi * HDIM + col) = make_float2(v2, v3);
        }
    }
    load_w128(Wb, hw1, tid);
    for (int idx = tid; idx < 24 * 32; idx += 256) {
        int row = idx >> 5, c = idx & 31;
        float4 v = make_float4(0.f, 0.f, 0.f, 0.f);
        if (row < C) v = *reinterpret_cast<const float4*>(w2 + (size_t)row * HDIM + c * 4);
        W2s[row * KSTRIDE + c * 2 + 0] = pack_bf16(v.x, v.y);
        W2s[row * KSTRIDE + c * 2 + 1] = pack_bf16(v.z, v.w);
    }
    __syncthreads();

    // ---- t2 = relu(x @ hw1^T + hb1) -> At1 (bf16) ----
    zero_acc(acc);
    gemm128(Ah, Wb, acc, wm, wn, g, t4);
#pragma unroll
    for (int i = 0; i < 2; i++) {
        int rl = wm * 32 + i * 16 + g;
#pragma unroll
        for (int j = 0; j < 8; j++) {
            int col = wn * 64 + j * 8 + 2 * t4;
            float v0 = fmaxf(acc[i][j][0] + hb1[col], 0.f);
            float v1 = fmaxf(acc[i][j][1] + hb1[col + 1], 0.f);
            float v2 = fmaxf(acc[i][j][2] + hb1[col], 0.f);
            float v3 = fmaxf(acc[i][j][3] + hb1[col + 1], 0.f);
            At1[rl * KSTRIDE + (col >> 1)] = pack_bf16(v0, v1);
            At1[(rl + 8) * KSTRIDE + (col >> 1)] = pack_bf16(v2, v3);
        }
    }
    __syncthreads();

    // ---- head logits: t2 @ w2^T (128 x 24 via mma, warps 0-3) ----
    if (wid < 4) {
        float hacc[2][3][4];
#pragma unroll
        for (int i = 0; i < 2; i++)
#pragma unroll
            for (int j = 0; j < 3; j++)
#pragma unroll
                for (int r = 0; r < 4; r++) hacc[i][j][r] = 0.f;
#pragma unroll
        for (int ks = 0; ks < 8; ks++) {
            int kb = ks * 8;
            unsigned af[2][4];
#pragma unroll
            for (int i = 0; i < 2; i++) {
                int rb = wm * 32 + i * 16;
                af[i][0] = At1[(rb + g) * KSTRIDE + kb + t4];
                af[i][1] = At1[(rb + 8 + g) * KSTRIDE + kb + t4];
                af[i][2] = At1[(rb + g) * KSTRIDE + kb + t4 + 4];
                af[i][3] = At1[(rb + 8 + g) * KSTRIDE + kb + t4 + 4];
            }
            unsigned bf[3][2];
#pragma unroll
            for (int j = 0; j < 3; j++) {
                int nb = j * 8;
                bf[j][0] = W2s[(nb + g) * KSTRIDE + kb + t4];
                bf[j][1] = W2s[(nb + g) * KSTRIDE + kb + t4 + 4];
            }
#pragma unroll
            for (int i = 0; i < 2; i++)
#pragma unroll
                for (int j = 0; j < 3; j++)
                    mma_bf16(hacc[i][j], af[i], bf[j]);
        }
#pragma unroll
        for (int i = 0; i < 2; i++) {
            int rl = wm * 32 + i * 16 + g;
#pragma unroll
            for (int j = 0; j < 3; j++) {
                int col = j * 8 + 2 * t4;
                logit[rl * 28 + col] = hacc[i][j][0];
                logit[rl * 28 + col + 1] = hacc[i][j][1];
                logit[(rl + 8) * 28 + col] = hacc[i][j][2];
                logit[(rl + 8) * 28 + col + 1] = hacc[i][j][3];
            }
        }
    }
    __syncthreads();

    // ---- softmax / log_softmax per node (warp per 16 nodes) ----
    for (int k = 0; k < 16; k++) {
        int nl = wid * 16 + k;
        int gm = m0 + nl;
        float myval = (lane < C) ? (logit[nl * 28 + lane] + bh2[lane]) : 0.f;
        float mx = (lane < C) ? myval : -INFINITY;
#pragma unroll
        for (int o = 16; o; o >>= 1) mx = fmaxf(mx, __shfl_xor_sync(0xffffffffu, mx, o));
        float e = (lane < C) ? expf(myval - mx) : 0.f;
        float s = e;
#pragma unroll
        for (int o = 16; o; o >>= 1) s += __shfl_xor_sync(0xffffffffu, s, o);
        if (gm < M && lane < C) {
            olog [(size_t)gm * C + lane] = myval - mx - logf(s);
            osoft[(size_t)gm * C + lane] = e / s;
        }
    }
}
#define GIN_SMEM ((3 * TILE_U32 + 24 * KSTRIDE + 128 + 128 * 28) * 4)

// ---------------- launch ----------------
extern "C" void kernel_launch(void* const* d_in, const int* in_sizes, int n_in,
                              void* d_out, int out_size) {
    const float* features = (const float*)d_in[0];
    const int*   eidx     = (const int*)  d_in[1];
    const float* ew       = (const float*)d_in[2];
    const float* w1       = (const float*)d_in[3];
    const float* b1       = (const float*)d_in[4];
    const float* gin_w1   = (const float*)d_in[5];
    const float* gin_b1   = (const float*)d_in[6];
    const float* gin_w2   = (const float*)d_in[7];
    const float* gin_b2   = (const float*)d_in[8];
    const float* gru_wih  = (const float*)d_in[9];
    const float* gru_whh  = (const float*)d_in[10];
    const float* gru_bih  = (const float*)d_in[11];
    const float* gru_bhh  = (const float*)d_in[12];
    const float* head_w1  = (const float*)d_in[13];
    const float* head_b1  = (const float*)d_in[14];
    const float* hw2_0    = (const float*)d_in[15];
    const float* hb2_0    = (const float*)d_in[16];
    const float* hw2_1    = (const float*)d_in[17];
    const float* hb2_1    = (const float*)d_in[18];
    const float* hw2_2    = (const float*)d_in[19];
    const float* hb2_2    = (const float*)d_in[20];

    float* out = (float*)d_out;

    float *p_x, *p_agg, *p_h, *p_csr_w;
    int *p_rowptr, *p_cursor, *p_bsum, *p_boff, *p_csr_src;
    cudaGetSymbolAddress((void**)&p_x,      g_x);
    cudaGetSymbolAddress((void**)&p_agg,    g_agg);
    cudaGetSymbolAddress((void**)&p_h,      g_h);
    cudaGetSymbolAddress((void**)&p_rowptr, g_rowptr);
    cudaGetSymbolAddress((void**)&p_cursor, g_cursor);
    cudaGetSymbolAddress((void**)&p_bsum,   g_blocksum);
    cudaGetSymbolAddress((void**)&p_boff,   g_blockoff);
    cudaGetSymbolAddress((void**)&p_csr_src,g_csr_src);
    cudaGetSymbolAddress((void**)&p_csr_w,  g_csr_w);

    cudaFuncSetAttribute(k_gemm_b<true>,  cudaFuncAttributeMaxDynamicSharedMemorySize, GEMM_SMEM);
    cudaFuncSetAttribute(k_gru_fused,     cudaFuncAttributeMaxDynamicSharedMemorySize, GRU_SMEM);
    cudaFuncSetAttribute(k_gin_head<2>,   cudaFuncAttributeMaxDynamicSharedMemorySize, GIN_SMEM);
    cudaFuncSetAttribute(k_gin_head<6>,   cudaFuncAttributeMaxDynamicSharedMemorySize, GIN_SMEM);
    cudaFuncSetAttribute(k_gin_head<21>,  cudaFuncAttributeMaxDynamicSharedMemorySize, GIN_SMEM);

    const int M = NNODES;
    const int E = NEDGES;
    const int tile_gx = (M + 127) / 128;                   // 782
    const int warp_blocks = (M * 32 + 255) / 256;
    const int edge_blocks = (E + 255) / 256;
    const int node_blocks = (M + 255) / 256;

    const int* e_dst = eidx;
    const int* e_src = eidx + E;

    const size_t o_log0 = 0;
    const size_t o_log1 = (size_t)M * 2;
    const size_t o_log2 = (size_t)M * 8;
    const size_t o_soft = (size_t)M * 29;

    // ---- build CSR ----
    k_deg_zero<<<node_blocks, 256>>>(p_cursor, M);
    k_hist<<<edge_blocks, 256>>>(e_dst, p_cursor, E);
    k_scan_local<<<NSCANB, SCAN_B>>>(p_cursor, p_rowptr, p_bsum, M);
    k_scan_block<<<1, 32>>>(p_bsum, p_boff, p_rowptr, NSCANB, M);
    k_scan_add<<<node_blocks, 256>>>(p_rowptr, p_cursor, p_boff, M);
    k_scatter<<<edge_blocks, 256>>>(e_dst, e_src, ew, p_cursor, p_csr_src, p_csr_w, E);

    // x = relu(features @ w1^T + b1)
    k_gemm_b<true><<<dim3(tile_gx, 1), 256, GEMM_SMEM>>>(features, w1, b1, p_x, M, HDIM);

    for (int i = 0; i < NL; i++) {
        k_spmm_csr<<<warp_blocks, 256>>>(p_rowptr, p_csr_src, p_csr_w, p_x, p_agg, M);

        k_gru_fused<<<tile_gx, 256, GRU_SMEM>>>(
            p_agg, p_x,
            gru_wih + (size_t)i * 384 * HDIM, gru_whh + (size_t)i * 384 * HDIM,
            gru_bih + (size_t)i * 384, gru_bhh + (size_t)i * 384,
            p_h, M);

        if (i == 0)
            k_gin_head<2><<<tile_gx, 256, GIN_SMEM>>>(
                p_h, gin_w1, gin_b1, gin_w2, gin_b2,
                head_w1, head_b1, hw2_0, hb2_0,
                p_x, out + o_log0, out + o_soft, M);
        else if (i == 1)
            k_gin_head<6><<<tile_gx, 256, GIN_SMEM>>>(
                p_h,
                gin_w1 + (size_t)1 * HDIM * HDIM, gin_b1 + HDIM,
                gin_w2 + (size_t)1 * HDIM * HDIM, gin_b2 + HDIM,
                head_w1 + (size_t)1 * HDIM * HDIM, head_b1 + HDIM, hw2_1, hb2_1,
                p_x, out + o_log1, out + o_soft + (size_t)M * 2, M);
        else
            k_gin_head<21><<<tile_gx, 256, GIN_SMEM>>>(
                p_h,
                gin_w1 + (size_t)2 * HDIM * HDIM, gin_b1 + 2 * HDIM,
                gin_w2 + (size_t)2 * HDIM * HDIM, gin_b2 + 2 * HDIM,
                head_w1 + (size_t)2 * HDIM * HDIM, head_b1 + 2 * HDIM, hw2_2, hb2_2,
                p_x, out + o_log2, out + o_soft + (size_t)M * 8, M);
    }
}

// round 8
// speedup vs baseline: 5.1148x; 1.0249x over previous
#include <cuda_runtime.h>
#include <cuda_bf16.h>
#include <math.h>

#define NNODES 100000
#define NEDGES 1600000
#define HDIM   128
#define NL     3
#define SCAN_B 512
#define NSCANB ((NNODES + SCAN_B - 1) / SCAN_B)   // 196

#define KSTRIDE 68                 // smem row stride in u32 (64 bf16-pairs + pad 4)
#define TILE_U32 (128 * KSTRIDE)   // one 128x128 bf16 tile in u32

// prepacked bf16 weight buffer offsets (u32 units)
#define OFF_WIH 0
#define OFF_WHH (OFF_WIH + 3 * 384 * 64)
#define OFF_GW1 (OFF_WHH + 3 * 384 * 64)
#define OFF_GW2 (OFF_GW1 + 3 * 128 * 64)
#define OFF_HW1 (OFF_GW2 + 3 * 128 * 64)
#define WB_TOTAL (OFF_HW1 + 3 * 128 * 64)

// ---------------- scratch (no allocations allowed) ----------------
__device__ float    g_x  [(size_t)NNODES * HDIM];       // f32 x (for z*x term)
__device__ unsigned g_xb [(size_t)NNODES * 64];         // bf16 x
__device__ unsigned g_aggb[(size_t)NNODES * 64];        // bf16 agg
__device__ unsigned g_hb [(size_t)NNODES * 64];         // bf16 h
__device__ unsigned g_wb [WB_TOTAL];                    // prepacked weights
// CSR scratch
__device__ int   g_rowptr[NNODES + 1];
__device__ int   g_cursor[NNODES];
__device__ int   g_blocksum[NSCANB];
__device__ int   g_blockoff[NSCANB];
__device__ int   g_csr_src[NEDGES];
__device__ float g_csr_w  [NEDGES];

// ---------------- helpers ----------------
__device__ __forceinline__ unsigned pack_bf16(float a, float b) {
    __nv_bfloat162 t = __floats2bfloat162_rn(a, b);
    return *reinterpret_cast<unsigned*>(&t);
}

__device__ __forceinline__ void mma_bf16(float* d, const unsigned* a, const unsigned* b) {
    asm volatile(
        "mma.sync.aligned.m16n8k16.row.col.f32.bf16.bf16.f32 "
        "{%0,%1,%2,%3}, {%4,%5,%6,%7}, {%8,%9}, {%0,%1,%2,%3};\n"
        : "+f"(d[0]), "+f"(d[1]), "+f"(d[2]), "+f"(d[3])
        : "r"(a[0]), "r"(a[1]), "r"(a[2]), "r"(a[3]), "r"(b[0]), "r"(b[1]));
}

__device__ __forceinline__ void cpa16(unsigned* smem_dst, const unsigned* g, bool valid) {
    unsigned saddr = (unsigned)__cvta_generic_to_shared(smem_dst);
    int sz = valid ? 16 : 0;
    asm volatile("cp.async.cg.shared.global [%0], [%1], 16, %2;\n"
                 :: "r"(saddr), "l"(g), "r"(sz) : "memory");
}
__device__ __forceinline__ void cpa_commit() {
    asm volatile("cp.async.commit_group;\n" ::: "memory");
}
__device__ __forceinline__ void cpa_wait0() {
    asm volatile("cp.async.wait_group 0;\n" ::: "memory");
}
__device__ __forceinline__ void cpa_wait1() {
    asm volatile("cp.async.wait_group 1;\n" ::: "memory");
}

// async copy of a 128x64u32 bf16 tile (rows row0..row0+127 of src, OOB rows zero-filled)
__device__ __forceinline__ void cpa_tile(unsigned* dst, const unsigned* __restrict__ src,
                                         int row0, int Mrows, int tid) {
#pragma unroll
    for (int p = 0; p < 8; p++) {
        int F = p * 256 + tid;
        int row = F >> 4;             // 16 chunks of 16B per row
        int c4 = (F & 15) * 4;
        bool v = (row0 + row) < Mrows;
        cpa16(dst + row * KSTRIDE + c4, src + (size_t)(row0 + row) * 64 + c4, v);
    }
}

// accumulate 128x128x128: acc += A_tile @ W_tile^T (warp fragments)
__device__ __forceinline__ void gemm128(const unsigned* __restrict__ As,
                                        const unsigned* __restrict__ Ws,
                                        float acc[2][8][4],
                                        int wm, int wn, int g, int t4) {
#pragma unroll
    for (int ks = 0; ks < 8; ks++) {
        int kb = ks * 8;
        unsigned af[2][4];
#pragma unroll
        for (int i = 0; i < 2; i++) {
            int rb = wm * 32 + i * 16;
            af[i][0] = As[(rb + g) * KSTRIDE + kb + t4];
            af[i][1] = As[(rb + 8 + g) * KSTRIDE + kb + t4];
            af[i][2] = As[(rb + g) * KSTRIDE + kb + t4 + 4];
            af[i][3] = As[(rb + 8 + g) * KSTRIDE + kb + t4 + 4];
        }
        unsigned bf[8][2];
#pragma unroll
        for (int j = 0; j < 8; j++) {
            int nb = wn * 64 + j * 8;
            bf[j][0] = Ws[(nb + g) * KSTRIDE + kb + t4];
            bf[j][1] = Ws[(nb + g) * KSTRIDE + kb + t4 + 4];
        }
#pragma unroll
        for (int i = 0; i < 2; i++)
#pragma unroll
            for (int j = 0; j < 8; j++)
                mma_bf16(acc[i][j], af[i], bf[j]);
    }
}

__device__ __forceinline__ void zero_acc(float acc[2][8][4]) {
#pragma unroll
    for (int i = 0; i < 2; i++)
#pragma unroll
        for (int j = 0; j < 8; j++)
#pragma unroll
            for (int r = 0; r < 4; r++) acc[i][j][r] = 0.f;
}

// load 128x128 f32 tile -> bf16 smem (for mlp1 features)
__device__ __forceinline__ void load_tile_g(unsigned* dst, const float* __restrict__ src,
                                            int row0, int M, int tid) {
#pragma unroll
    for (int p = 0; p < 16; p++) {
        int F = p * 256 + tid;
        int row = F >> 5, c = F & 31;
        float4 v = make_float4(0.f, 0.f, 0.f, 0.f);
        if (row0 + row < M) v = *reinterpret_cast<const float4*>(src + (size_t)(row0 + row) * HDIM + c * 4);
        dst[row * KSTRIDE + c * 2 + 0] = pack_bf16(v.x, v.y);
        dst[row * KSTRIDE + c * 2 + 1] = pack_bf16(v.z, v.w);
    }
}

__device__ __forceinline__ void load_w128_f32(unsigned* dst, const float* __restrict__ src, int tid) {
#pragma unroll
    for (int p = 0; p < 16; p++) {
        int F = p * 256 + tid;
        int row = F >> 5, c = F & 31;
        float4 v = *reinterpret_cast<const float4*>(src + (size_t)row * HDIM + c * 4);
        dst[row * KSTRIDE + c * 2 + 0] = pack_bf16(v.x, v.y);
        dst[row * KSTRIDE + c * 2 + 1] = pack_bf16(v.z, v.w);
    }
}

__device__ __forceinline__ float sigm(float x) { return 1.f / (1.f + expf(-x)); }

// ---------------- weight prepack ----------------
__global__ void k_pack(const float4* __restrict__ src, uint2* __restrict__ dst, int n4) {
    int i = blockIdx.x * blockDim.x + threadIdx.x;
    if (i < n4) {
        float4 v = src[i];
        dst[i] = make_uint2(pack_bf16(v.x, v.y), pack_bf16(v.z, v.w));
    }
}

// ---------------- CSR build ----------------
__global__ void k_deg_zero(int* deg, int n) {
    int i = blockIdx.x * blockDim.x + threadIdx.x;
    if (i < n) deg[i] = 0;
}

__global__ void k_hist(const int* __restrict__ dst, int* __restrict__ deg, int E) {
    int i = blockIdx.x * blockDim.x + threadIdx.x;
    if (i < E) atomicAdd(&deg[dst[i]], 1);
}

__global__ __launch_bounds__(SCAN_B) void k_scan_local(const int* __restrict__ deg,
                                                       int* __restrict__ rowptr,
                                                       int* __restrict__ blocksum, int n) {
    __shared__ int s[SCAN_B];
    int tid = threadIdx.x;
    int i = blockIdx.x * SCAN_B + tid;
    int v = (i < n) ? deg[i] : 0;
    s[tid] = v;
    __syncthreads();
    for (int off = 1; off < SCAN_B; off <<= 1) {
        int t = (tid >= off) ? s[tid - off] : 0;
        __syncthreads();
        s[tid] += t;
        __syncthreads();
    }
    if (i < n) rowptr[i] = s[tid] - v;
    if (tid == SCAN_B - 1) blocksum[blockIdx.x] = s[tid];
}

__global__ void k_scan_block(const int* __restrict__ blocksum, int* __restrict__ blockoff,
                             int* __restrict__ rowptr, int nblk, int n) {
    if (threadIdx.x == 0 && blockIdx.x == 0) {
        int acc = 0;
        for (int b = 0; b < nblk; b++) { blockoff[b] = acc; acc += blocksum[b]; }
        rowptr[n] = acc;
    }
}

__global__ void k_scan_add(int* __restrict__ rowptr, int* __restrict__ cursor,
                           const int* __restrict__ blockoff, int n) {
    int i = blockIdx.x * blockDim.x + threadIdx.x;
    if (i < n) {
        int v = rowptr[i] + blockoff[i / SCAN_B];
        rowptr[i] = v;
        cursor[i] = v;
    }
}

__global__ void k_scatter(const int* __restrict__ dst, const int* __restrict__ src,
                          const float* __restrict__ ew, int* __restrict__ cursor,
                          int* __restrict__ csr_src, float* __restrict__ csr_w, int E) {
    int i = blockIdx.x * blockDim.x + threadIdx.x;
    if (i < E) {
        int pos = atomicAdd(&cursor[dst[i]], 1);
        csr_src[pos] = src[i];
        csr_w[pos] = ew[i];
    }
}

// ---------------- SpMM (CSR, warp per node, bf16 gather, bf16 out) ----------------
__global__ __launch_bounds__(256) void k_spmm_b(
    const int* __restrict__ rowptr, const int* __restrict__ csr_src,
    const float* __restrict__ csr_w, const unsigned* __restrict__ xb,
    unsigned* __restrict__ aggb, int n) {
    int row = (blockIdx.x * blockDim.x + threadIdx.x) >> 5;
    int lane = threadIdx.x & 31;
    if (row >= n) return;
    int e = rowptr[row];
    int end = rowptr[row + 1];
    float a0 = 0.f, a1 = 0.f, a2 = 0.f, a3 = 0.f;
    for (; e < end; e++) {
        int s0 = csr_src[e];
        float w0 = csr_w[e];
        uint2 v = *reinterpret_cast<const uint2*>(xb + (size_t)s0 * 64 + lane * 2);
        float f0 = __uint_as_float(v.x << 16);
        float f1 = __uint_as_float(v.x & 0xffff0000u);
        float f2 = __uint_as_float(v.y << 16);
        float f3 = __uint_as_float(v.y & 0xffff0000u);
        a0 = fmaf(w0, f0, a0);
        a1 = fmaf(w0, f1, a1);
        a2 = fmaf(w0, f2, a2);
        a3 = fmaf(w0, f3, a3);
    }
    *reinterpret_cast<uint2*>(aggb + (size_t)row * 64 + lane * 2) =
        make_uint2(pack_bf16(a0, a1), pack_bf16(a2, a3));
}

// ---------------- mlp1 GEMM: x = relu(features @ w1^T + b1), writes f32 + bf16 ----------------
__global__ __launch_bounds__(256) void k_gemm_mlp1(
    const float* __restrict__ A, const float* __restrict__ W,
    const float* __restrict__ bias, float* __restrict__ C,
    unsigned* __restrict__ Cb, int M)
{
    extern __shared__ unsigned smem_u[];
    unsigned* As = smem_u;
    unsigned* Ws = smem_u + TILE_U32;

    const int tid = threadIdx.x;
    const int wid = tid >> 5;
    const int lane = tid & 31;
    const int g = lane >> 2;
    const int t4 = lane & 3;
    const int wm = wid & 3;
    const int wn = wid >> 2;
    const int m0 = blockIdx.x * 128;

    load_tile_g(As, A, m0, M, tid);
    load_w128_f32(Ws, W, tid);
    __syncthreads();

    float acc[2][8][4];
    zero_acc(acc);
    gemm128(As, Ws, acc, wm, wn, g, t4);

#pragma unroll
    for (int i = 0; i < 2; i++) {
        int row_lo = m0 + wm * 32 + i * 16 + g;
        int row_hi = row_lo + 8;
#pragma unroll
        for (int j = 0; j < 8; j++) {
            int col = wn * 64 + j * 8 + 2 * t4;
            float b0 = bias[col];
            float b1 = bias[col + 1];
            if (row_lo < M) {
                float v0 = fmaxf(acc[i][j][0] + b0, 0.f);
                float v1 = fmaxf(acc[i][j][1] + b1, 0.f);
                *reinterpret_cast<float2*>(C + (size_t)row_lo * HDIM + col) = make_float2(v0, v1);
                Cb[(size_t)row_lo * 64 + (col >> 1)] = pack_bf16(v0, v1);
            }
            if (row_hi < M) {
                float v2 = fmaxf(acc[i][j][2] + b0, 0.f);
                float v3 = fmaxf(acc[i][j][3] + b1, 0.f);
                *reinterpret_cast<float2*>(C + (size_t)row_hi * HDIM + col) = make_float2(v2, v3);
                Cb[(size_t)row_hi * 64 + (col >> 1)] = pack_bf16(v2, v3);
            }
        }
    }
}
#define GEMM_SMEM (2 * TILE_U32 * 4)

// ---------------- fused GRU (double-buffered cp.async weight stream) ----------------
__global__ __launch_bounds__(256, 1) void k_gru_fused(
    const unsigned* __restrict__ aggb, const unsigned* __restrict__ xb,
    const float* __restrict__ xf,
    const unsigned* __restrict__ wihb, const unsigned* __restrict__ whhb,
    const float* __restrict__ bih, const float* __restrict__ bhh,
    unsigned* __restrict__ hb, int M)
{
    extern __shared__ unsigned sm[];
    unsigned* Aagg = sm;
    unsigned* Ax   = sm + TILE_U32;
    unsigned* Wb0  = sm + 2 * TILE_U32;
    unsigned* Wb1  = sm + 3 * TILE_U32;

    const int tid = threadIdx.x;
    const int wid = tid >> 5;
    const int lane = tid & 31;
    const int g = lane >> 2;
    const int t4 = lane & 3;
    const int wm = wid & 3;
    const int wn = wid >> 2;
    const int m0 = blockIdx.x * 128;

    // chunk order: wih1(agg), whh1(x) -> z ; wih0(agg), whh0(x) -> r ; whh2(x), wih2(agg) -> n
    const unsigned* wc0 = wihb + 128 * 64;
    const unsigned* wc1 = whhb + 128 * 64;
    const unsigned* wc2 = wihb;
    const unsigned* wc3 = whhb;
    const unsigned* wc4 = whhb + 256 * 64;
    const unsigned* wc5 = wihb + 256 * 64;

    cpa_tile(Aagg, aggb, m0, M, tid);
    cpa_tile(Ax,   xb,   m0, M, tid);
    cpa_tile(Wb0, wc0, 0, 128, tid);
    cpa_commit();                      // G0: tiles + w0
    cpa_tile(Wb1, wc1, 0, 128, tid);
    cpa_commit();                      // G1: w1

    float zf[2][8][4], rf[2][8][4], acc[2][8][4];

    // chunk0: gi1 (Aagg x wih1)
    zero_acc(acc);
    cpa_wait1(); __syncthreads();
    gemm128(Aagg, Wb0, acc, wm, wn, g, t4);
    __syncthreads();
    cpa_tile(Wb0, wc2, 0, 128, tid); cpa_commit();   // G2
    // chunk1: + gh1 (Ax x whh1) -> z
    cpa_wait1(); __syncthreads();
    gemm128(Ax, Wb1, acc, wm, wn, g, t4);
#pragma unroll
    for (int i = 0; i < 2; i++)
#pragma unroll
        for (int j = 0; j < 8; j++)
#pragma unroll
            for (int r = 0; r < 4; r++) {
                int col = wn * 64 + j * 8 + 2 * t4 + (r & 1);
                zf[i][j][r] = sigm(acc[i][j][r] + bih[128 + col] + bhh[128 + col]);
            }
    __syncthreads();
    cpa_tile(Wb1, wc3, 0, 128, tid); cpa_commit();   // G3

    // chunk2: gi0 (Aagg x wih0)
    zero_acc(acc);
    cpa_wait1(); __syncthreads();
    gemm128(Aagg, Wb0, acc, wm, wn, g, t4);
    __syncthreads();
    cpa_tile(Wb0, wc4, 0, 128, tid); cpa_commit();   // G4
    // chunk3: + gh0 (Ax x whh0) -> r
    cpa_wait1(); __syncthreads();
    gemm128(Ax, Wb1, acc, wm, wn, g, t4);
#pragma unroll
    for (int i = 0; i < 2; i++)
#pragma unroll
        for (int j = 0; j < 8; j++)
#pragma unroll
            for (int r = 0; r < 4; r++) {
                int col = wn * 64 + j * 8 + 2 * t4 + (r & 1);
                rf[i][j][r] = sigm(acc[i][j][r] + bih[col] + bhh[col]);
            }
    __syncthreads();
    cpa_tile(Wb1, wc5, 0, 128, tid); cpa_commit();   // G5

    // chunk4: gh2 (Ax x whh2); acc = r*(gh2+bhh2)
    zero_acc(acc);
    cpa_wait1(); __syncthreads();
    gemm128(Ax, Wb0, acc, wm, wn, g, t4);
#pragma unroll
    for (int i = 0; i < 2; i++)
#pragma unroll
        for (int j = 0; j < 8; j++)
#pragma unroll
            for (int r = 0; r < 4; r++) {
                int col = wn * 64 + j * 8 + 2 * t4 + (r & 1);
                acc[i][j][r] = rf[i][j][r] * (acc[i][j][r] + bhh[256 + col]);
            }
    // chunk5: + gi2 (Aagg x wih2)
    cpa_wait0(); __syncthreads();
    gemm128(Aagg, Wb1, acc, wm, wn, g, t4);

    // h = (1-z)*tanh(acc + bih2) + z*x  (bf16 out)
#pragma unroll
    for (int i = 0; i < 2; i++) {
        int row_lo = m0 + wm * 32 + i * 16 + g;
        int row_hi = row_lo + 8;
#pragma unroll
        for (int j = 0; j < 8; j++) {
            int col = wn * 64 + j * 8 + 2 * t4;
            if (row_lo < M) {
                float2 xv = *reinterpret_cast<const float2*>(xf + (size_t)row_lo * HDIM + col);
                float n0v = tanhf(acc[i][j][0] + bih[256 + col]);
                float n1v = tanhf(acc[i][j][1] + bih[256 + col + 1]);
                float h0 = (1.f - zf[i][j][0]) * n0v + zf[i][j][0] * xv.x;
                float h1 = (1.f - zf[i][j][1]) * n1v + zf[i][j][1] * xv.y;
                hb[(size_t)row_lo * 64 + (col >> 1)] = pack_bf16(h0, h1);
            }
            if (row_hi < M) {
                float2 xv = *reinterpret_cast<const float2*>(xf + (size_t)row_hi * HDIM + col);
                float n2v = tanhf(acc[i][j][2] + bih[256 + col]);
                float n3v = tanhf(acc[i][j][3] + bih[256 + col + 1]);
                float h2 = (1.f - zf[i][j][2]) * n2v + zf[i][j][2] * xv.x;
                float h3 = (1.f - zf[i][j][3]) * n3v + zf[i][j][3] * xv.y;
                hb[(size_t)row_hi * 64 + (col >> 1)] = pack_bf16(h2, h3);
            }
        }
    }
}
#define GRU_SMEM (4 * TILE_U32 * 4)

// ---------------- fused GIN MLP + norm + head + softmax ----------------
template <int C>
__global__ __launch_bounds__(256, 1) void k_gin_head(
    const unsigned* __restrict__ hbt,
    const unsigned* __restrict__ g1b, const float* __restrict__ b1v,
    const unsigned* __restrict__ g2b, const float* __restrict__ b2v,
    const unsigned* __restrict__ hw1b, const float* __restrict__ hb1,
    const float* __restrict__ w2, const float* __restrict__ bh2,
    float* __restrict__ xout, unsigned* __restrict__ xbout,
    float* __restrict__ olog, float* __restrict__ osoft,
    int M)
{
    extern __shared__ unsigned sm[];
    unsigned* Ah   = sm;                       // h tile / later x tile
    unsigned* At1  = sm + TILE_U32;            // t1 / t2
    unsigned* Wb0  = sm + 2 * TILE_U32;        // g1, later hw1
    unsigned* Wb1  = sm + 3 * TILE_U32;        // g2
    unsigned* W2s  = sm + 4 * TILE_U32;        // head w2 (24 rows)
    float* rowsum  = reinterpret_cast<float*>(W2s + 24 * KSTRIDE);  // [128]
    float* logit   = rowsum + 128;             // [128][28]

    const int tid = threadIdx.x;
    const int wid = tid >> 5;
    const int lane = tid & 31;
    const int g = lane >> 2;
    const int t4 = lane & 3;
    const int wm = wid & 3;
    const int wn = wid >> 2;
    const int m0 = blockIdx.x * 128;

    if (tid < 128) rowsum[tid] = 0.f;
    cpa_tile(Ah, hbt, m0, M, tid);
    cpa_tile(Wb0, g1b, 0, 128, tid);
    cpa_commit();                      // G0
    cpa_tile(Wb1, g2b, 0, 128, tid);
    cpa_commit();                      // G1

    float acc[2][8][4];

    // ---- t1 = relu(h @ g1^T + b1) ----
    zero_acc(acc);
    cpa_wait1(); __syncthreads();
    gemm128(Ah, Wb0, acc, wm, wn, g, t4);
#pragma unroll
    for (int i = 0; i < 2; i++) {
        int rl = wm * 32 + i * 16 + g;
#pragma unroll
        for (int j = 0; j < 8; j++) {
            int col = wn * 64 + j * 8 + 2 * t4;
            float v0 = fmaxf(acc[i][j][0] + b1v[col], 0.f);
            float v1 = fmaxf(acc[i][j][1] + b1v[col + 1], 0.f);
            float v2 = fmaxf(acc[i][j][2] + b1v[col], 0.f);
            float v3 = fmaxf(acc[i][j][3] + b1v[col + 1], 0.f);
            At1[rl * KSTRIDE + (col >> 1)] = pack_bf16(v0, v1);
            At1[(rl + 8) * KSTRIDE + (col >> 1)] = pack_bf16(v2, v3);
        }
    }
    __syncthreads();
    cpa_tile(Wb0, hw1b, 0, 128, tid); cpa_commit();   // G2

    // ---- x = relu(t1 @ g2^T + b2), rowsum ----
    zero_acc(acc);
    cpa_wait1(); __syncthreads();
    gemm128(At1, Wb1, acc, wm, wn, g, t4);
#pragma unroll
    for (int i = 0; i < 2; i++) {
        float s_lo = 0.f, s_hi = 0.f;
#pragma unroll
        for (int j = 0; j < 8; j++) {
            int col = wn * 64 + j * 8 + 2 * t4;
            acc[i][j][0] = fmaxf(acc[i][j][0] + b2v[col], 0.f);
            acc[i][j][1] = fmaxf(acc[i][j][1] + b2v[col + 1], 0.f);
            acc[i][j][2] = fmaxf(acc[i][j][2] + b2v[col], 0.f);
            acc[i][j][3] = fmaxf(acc[i][j][3] + b2v[col + 1], 0.f);
            s_lo += acc[i][j][0] * acc[i][j][0] + acc[i][j][1] * acc[i][j][1];
            s_hi += acc[i][j][2] * acc[i][j][2] + acc[i][j][3] * acc[i][j][3];
        }
        atomicAdd(&rowsum[wm * 32 + i * 16 + g], s_lo);
        atomicAdd(&rowsum[wm * 32 + i * 16 + 8 + g], s_hi);
    }
    __syncthreads();

    // ---- normalize, write x (f32+bf16), repack to Ah; load W2s ----
#pragma unroll
    for (int i = 0; i < 2; i++) {
        int rl = wm * 32 + i * 16 + g;
        float inv_lo = rsqrtf(1.f + rowsum[rl]);
        float inv_hi = rsqrtf(1.f + rowsum[rl + 8]);
        int gm_lo = m0 + rl;
        int gm_hi = gm_lo + 8;
#pragma unroll
        for (int j = 0; j < 8; j++) {
            int col = wn * 64 + j * 8 + 2 * t4;
            float v0 = acc[i][j][0] * inv_lo;
            float v1 = acc[i][j][1] * inv_lo;
            float v2 = acc[i][j][2] * inv_hi;
            float v3 = acc[i][j][3] * inv_hi;
            unsigned p_lo = pack_bf16(v0, v1);
            unsigned p_hi = pack_bf16(v2, v3);
            Ah[rl * KSTRIDE + (col >> 1)] = p_lo;
            Ah[(rl + 8) * KSTRIDE + (col >> 1)] = p_hi;
            if (gm_lo < M) {
                *reinterpret_cast<float2*>(xout + (size_t)gm_lo * HDIM + col) = make_float2(v0, v1);
                xbout[(size_t)gm_lo * 64 + (col >> 1)] = p_lo;
            }
            if (gm_hi < M) {
                *reinterpret_cast<float2*>(xout + (size_t)gm_hi * HDIM + col) = make_float2(v2, v3);
                xbout[(size_t)gm_hi * 64 + (col >> 1)] = p_hi;
            }
        }
    }
    for (int idx = tid; idx < 24 * 32; idx += 256) {
        int row = idx >> 5, c = idx & 31;
        float4 v = make_float4(0.f, 0.f, 0.f, 0.f);
        if (row < C) v = *reinterpret_cast<const float4*>(w2 + (size_t)row * HDIM + c * 4);
        W2s[row * KSTRIDE + c * 2 + 0] = pack_bf16(v.x, v.y);
        W2s[row * KSTRIDE + c * 2 + 1] = pack_bf16(v.z, v.w);
    }
    __syncthreads();

    // ---- t2 = relu(x @ hw1^T + hb1) -> At1 ----
    zero_acc(acc);
    cpa_wait0(); __syncthreads();
    gemm128(Ah, Wb0, acc, wm, wn, g, t4);
#pragma unroll
    for (int i = 0; i < 2; i++) {
        int rl = wm * 32 + i * 16 + g;
#pragma unroll
        for (int j = 0; j < 8; j++) {
            int col = wn * 64 + j * 8 + 2 * t4;
            float v0 = fmaxf(acc[i][j][0] + hb1[col], 0.f);
            float v1 = fmaxf(acc[i][j][1] + hb1[col + 1], 0.f);
            float v2 = fmaxf(acc[i][j][2] + hb1[col], 0.f);
            float v3 = fmaxf(acc[i][j][3] + hb1[col + 1], 0.f);
            At1[rl * KSTRIDE + (col >> 1)] = pack_bf16(v0, v1);
            At1[(rl + 8) * KSTRIDE + (col >> 1)] = pack_bf16(v2, v3);
        }
    }
    __syncthreads();

    // ---- head logits: t2 @ w2^T (warps 0-3) ----
    if (wid < 4) {
        float hacc[2][3][4];
#pragma unroll
        for (int i = 0; i < 2; i++)
#pragma unroll
            for (int j = 0; j < 3; j++)
#pragma unroll
                for (int r = 0; r < 4; r++) hacc[i][j][r] = 0.f;
#pragma unroll
        for (int ks = 0; ks < 8; ks++) {
            int kb = ks * 8;
            unsigned af[2][4];
#pragma unroll
            for (int i = 0; i < 2; i++) {
                int rb = wm * 32 + i * 16;
                af[i][0] = At1[(rb + g) * KSTRIDE + kb + t4];
                af[i][1] = At1[(rb + 8 + g) * KSTRIDE + kb + t4];
                af[i][2] = At1[(rb + g) * KSTRIDE + kb + t4 + 4];
                af[i][3] = At1[(rb + 8 + g) * KSTRIDE + kb + t4 + 4];
            }
            unsigned bfr[3][2];
#pragma unroll
            for (int j = 0; j < 3; j++) {
                int nb = j * 8;
                bfr[j][0] = W2s[(nb + g) * KSTRIDE + kb + t4];
                bfr[j][1] = W2s[(nb + g) * KSTRIDE + kb + t4 + 4];
            }
#pragma unroll
            for (int i = 0; i < 2; i++)
#pragma unroll
                for (int j = 0; j < 3; j++)
                    mma_bf16(hacc[i][j], af[i], bfr[j]);
        }
#pragma unroll
        for (int i = 0; i < 2; i++) {
            int rl = wm * 32 + i * 16 + g;
#pragma unroll
            for (int j = 0; j < 3; j++) {
                int col = j * 8 + 2 * t4;
                logit[rl * 28 + col] = hacc[i][j][0];
                logit[rl * 28 + col + 1] = hacc[i][j][1];
                logit[(rl + 8) * 28 + col] = hacc[i][j][2];
                logit[(rl + 8) * 28 + col + 1] = hacc[i][j][3];
            }
        }
    }
    __syncthreads();

    // ---- softmax / log_softmax ----
    for (int k = 0; k < 16; k++) {
        int nl = wid * 16 + k;
        int gm = m0 + nl;
        float myval = (lane < C) ? (logit[nl * 28 + lane] + bh2[lane]) : 0.f;
        float mx = (lane < C) ? myval : -INFINITY;
#pragma unroll
        for (int o = 16; o; o >>= 1) mx = fmaxf(mx, __shfl_xor_sync(0xffffffffu, mx, o));
        float e = (lane < C) ? expf(myval - mx) : 0.f;
        float s = e;
#pragma unroll
        for (int o = 16; o; o >>= 1) s += __shfl_xor_sync(0xffffffffu, s, o);
        if (gm < M && lane < C) {
            olog [(size_t)gm * C + lane] = myval - mx - logf(s);
            osoft[(size_t)gm * C + lane] = e / s;
        }
    }
}
#define GIN_SMEM ((4 * TILE_U32 + 24 * KSTRIDE + 128 + 128 * 28) * 4)

// ---------------- launch ----------------
extern "C" void kernel_launch(void* const* d_in, const int* in_sizes, int n_in,
                              void* d_out, int out_size) {
    const float* features = (const float*)d_in[0];
    const int*   eidx     = (const int*)  d_in[1];
    const float* ew       = (const float*)d_in[2];
    const float* w1       = (const float*)d_in[3];
    const float* b1       = (const float*)d_in[4];
    const float* gin_w1   = (const float*)d_in[5];
    const float* gin_b1   = (const float*)d_in[6];
    const float* gin_w2   = (const float*)d_in[7];
    const float* gin_b2   = (const float*)d_in[8];
    const float* gru_wih  = (const float*)d_in[9];
    const float* gru_whh  = (const float*)d_in[10];
    const float* gru_bih  = (const float*)d_in[11];
    const float* gru_bhh  = (const float*)d_in[12];
    const float* head_w1  = (const float*)d_in[13];
    const float* head_b1  = (const float*)d_in[14];
    const float* hw2_0    = (const float*)d_in[15];
    const float* hb2_0    = (const float*)d_in[16];
    const float* hw2_1    = (const float*)d_in[17];
    const float* hb2_1    = (const float*)d_in[18];
    const float* hw2_2    = (const float*)d_in[19];
    const float* hb2_2    = (const float*)d_in[20];

    float* out = (float*)d_out;

    float *p_x, *p_csr_w;
    unsigned *p_xb, *p_aggb, *p_hb, *p_wb;
    int *p_rowptr, *p_cursor, *p_bsum, *p_boff, *p_csr_src;
    cudaGetSymbolAddress((void**)&p_x,      g_x);
    cudaGetSymbolAddress((void**)&p_xb,     g_xb);
    cudaGetSymbolAddress((void**)&p_aggb,   g_aggb);
    cudaGetSymbolAddress((void**)&p_hb,     g_hb);
    cudaGetSymbolAddress((void**)&p_wb,     g_wb);
    cudaGetSymbolAddress((void**)&p_rowptr, g_rowptr);
    cudaGetSymbolAddress((void**)&p_cursor, g_cursor);
    cudaGetSymbolAddress((void**)&p_bsum,   g_blocksum);
    cudaGetSymbolAddress((void**)&p_boff,   g_blockoff);
    cudaGetSymbolAddress((void**)&p_csr_src,g_csr_src);
    cudaGetSymbolAddress((void**)&p_csr_w,  g_csr_w);

    cudaFuncSetAttribute(k_gemm_mlp1,    cudaFuncAttributeMaxDynamicSharedMemorySize, GEMM_SMEM);
    cudaFuncSetAttribute(k_gru_fused,    cudaFuncAttributeMaxDynamicSharedMemorySize, GRU_SMEM);
    cudaFuncSetAttribute(k_gin_head<2>,  cudaFuncAttributeMaxDynamicSharedMemorySize, GIN_SMEM);
    cudaFuncSetAttribute(k_gin_head<6>,  cudaFuncAttributeMaxDynamicSharedMemorySize, GIN_SMEM);
    cudaFuncSetAttribute(k_gin_head<21>, cudaFuncAttributeMaxDynamicSharedMemorySize, GIN_SMEM);

    const int M = NNODES;
    const int E = NEDGES;
    const int tile_gx = (M + 127) / 128;
    const int warp_blocks = (M * 32 + 255) / 256;
    const int edge_blocks = (E + 255) / 256;
    const int node_blocks = (M + 255) / 256;

    const int* e_dst = eidx;
    const int* e_src = eidx + E;

    const size_t o_log0 = 0;
    const size_t o_log1 = (size_t)M * 2;
    const size_t o_log2 = (size_t)M * 8;
    const size_t o_soft = (size_t)M * 29;

    // ---- prepack weights to bf16 ----
    {
        int n4;
        n4 = 3 * 384 * HDIM / 4;
        k_pack<<<(n4 + 255) / 256, 256>>>((const float4*)gru_wih, (uint2*)(p_wb + OFF_WIH), n4);
        k_pack<<<(n4 + 255) / 256, 256>>>((const float4*)gru_whh, (uint2*)(p_wb + OFF_WHH), n4);
        n4 = 3 * HDIM * HDIM / 4;
        k_pack<<<(n4 + 255) / 256, 256>>>((const float4*)gin_w1,  (uint2*)(p_wb + OFF_GW1), n4);
        k_pack<<<(n4 + 255) / 256, 256>>>((const float4*)gin_w2,  (uint2*)(p_wb + OFF_GW2), n4);
        k_pack<<<(n4 + 255) / 256, 256>>>((const float4*)head_w1, (uint2*)(p_wb + OFF_HW1), n4);
    }

    // ---- build CSR ----
    k_deg_zero<<<node_blocks, 256>>>(p_cursor, M);
    k_hist<<<edge_blocks, 256>>>(e_dst, p_cursor, E);
    k_scan_local<<<NSCANB, SCAN_B>>>(p_cursor, p_rowptr, p_bsum, M);
    k_scan_block<<<1, 32>>>(p_bsum, p_boff, p_rowptr, NSCANB, M);
    k_scan_add<<<node_blocks, 256>>>(p_rowptr, p_cursor, p_boff, M);
    k_scatter<<<edge_blocks, 256>>>(e_dst, e_src, ew, p_cursor, p_csr_src, p_csr_w, E);

    // x = relu(features @ w1^T + b1)
    k_gemm_mlp1<<<tile_gx, 256, GEMM_SMEM>>>(features, w1, b1, p_x, p_xb, M);

    for (int i = 0; i < NL; i++) {
        k_spmm_b<<<warp_blocks, 256>>>(p_rowptr, p_csr_src, p_csr_w, p_xb, p_aggb, M);

        k_gru_fused<<<tile_gx, 256, GRU_SMEM>>>(
            p_aggb, p_xb, p_x,
            p_wb + OFF_WIH + (size_t)i * 384 * 64,
            p_wb + OFF_WHH + (size_t)i * 384 * 64,
            gru_bih + (size_t)i * 384, gru_bhh + (size_t)i * 384,
            p_hb, M);

        const unsigned* g1b  = p_wb + OFF_GW1 + (size_t)i * 128 * 64;
        const unsigned* g2b  = p_wb + OFF_GW2 + (size_t)i * 128 * 64;
        const unsigned* hw1b = p_wb + OFF_HW1 + (size_t)i * 128 * 64;
        if (i == 0)
            k_gin_head<2><<<tile_gx, 256, GIN_SMEM>>>(
                p_hb, g1b, gin_b1, g2b, gin_b2,
                hw1b, head_b1, hw2_0, hb2_0,
                p_x, p_xb, out + o_log0, out + o_soft, M);
        else if (i == 1)
            k_gin_head<6><<<tile_gx, 256, GIN_SMEM>>>(
                p_hb, g1b, gin_b1 + HDIM, g2b, gin_b2 + HDIM,
                hw1b, head_b1 + HDIM, hw2_1, hb2_1,
                p_x, p_xb, out + o_log1, out + o_soft + (size_t)M * 2, M);
        else
            k_gin_head<21><<<tile_gx, 256, GIN_SMEM>>>(
                p_hb, g1b, gin_b1 + 2 * HDIM, g2b, gin_b2 + 2 * HDIM,
                hw1b, head_b1 + 2 * HDIM, hw2_2, hb2_2,
                p_x, p_xb, out + o_log2, out + o_soft + (size_t)M * 8, M);
    }
}

// round 9
// speedup vs baseline: 6.0643x; 1.1856x over previous
#include <cuda_runtime.h>
#include <cuda_bf16.h>
#include <math.h>

#define NNODES 100000
#define NEDGES 1600000
#define HDIM   128
#define NL     3
#define SCAN_B 512
#define NSCANB ((NNODES + SCAN_B - 1) / SCAN_B)   // 196

#define KSTRIDE 68                 // smem row stride in u32 (64 bf16-pairs + pad 4)
#define TILE_U32 (128 * KSTRIDE)   // 128-row bf16 tile in u32
#define HTILE_U32 (64 * KSTRIDE)   // 64-row bf16 tile in u32

// prepacked bf16 weight buffer offsets (u32 units)
#define OFF_WIH 0
#define OFF_WHH (OFF_WIH + 3 * 384 * 64)
#define OFF_GW1 (OFF_WHH + 3 * 384 * 64)
#define OFF_GW2 (OFF_GW1 + 3 * 128 * 64)
#define OFF_HW1 (OFF_GW2 + 3 * 128 * 64)
#define WB_TOTAL (OFF_HW1 + 3 * 128 * 64)

// ---------------- scratch (no allocations allowed) ----------------
__device__ float    g_x  [(size_t)NNODES * HDIM];       // f32 x (for z*x term)
__device__ unsigned g_xb [(size_t)NNODES * 64];         // bf16 x
__device__ unsigned g_aggb[(size_t)NNODES * 64];        // bf16 agg
__device__ unsigned g_hb [(size_t)NNODES * 64];         // bf16 h
__device__ unsigned g_wb [WB_TOTAL];                    // prepacked weights
// CSR scratch
__device__ int   g_rowptr[NNODES + 1];
__device__ int   g_cursor[NNODES];
__device__ int   g_blocksum[NSCANB];
__device__ int   g_blockoff[NSCANB];
__device__ int2  g_csr_e[NEDGES];                       // {src, w_bits}

// ---------------- helpers ----------------
__device__ __forceinline__ unsigned pack_bf16(float a, float b) {
    __nv_bfloat162 t = __floats2bfloat162_rn(a, b);
    return *reinterpret_cast<unsigned*>(&t);
}

__device__ __forceinline__ void mma_bf16(float* d, const unsigned* a, const unsigned* b) {
    asm volatile(
        "mma.sync.aligned.m16n8k16.row.col.f32.bf16.bf16.f32 "
        "{%0,%1,%2,%3}, {%4,%5,%6,%7}, {%8,%9}, {%0,%1,%2,%3};\n"
        : "+f"(d[0]), "+f"(d[1]), "+f"(d[2]), "+f"(d[3])
        : "r"(a[0]), "r"(a[1]), "r"(a[2]), "r"(a[3]), "r"(b[0]), "r"(b[1]));
}

__device__ __forceinline__ void cpa16(unsigned* smem_dst, const unsigned* g, bool valid) {
    unsigned saddr = (unsigned)__cvta_generic_to_shared(smem_dst);
    int sz = valid ? 16 : 0;
    asm volatile("cp.async.cg.shared.global [%0], [%1], 16, %2;\n"
                 :: "r"(saddr), "l"(g), "r"(sz) : "memory");
}
__device__ __forceinline__ void cpa_commit() {
    asm volatile("cp.async.commit_group;\n" ::: "memory");
}
__device__ __forceinline__ void cpa_wait0() {
    asm volatile("cp.async.wait_group 0;\n" ::: "memory");
}
__device__ __forceinline__ void cpa_wait1() {
    asm volatile("cp.async.wait_group 1;\n" ::: "memory");
}

// 128-row tile async copy (weights)
__device__ __forceinline__ void cpa_tile(unsigned* dst, const unsigned* __restrict__ src,
                                         int tid) {
#pragma unroll
    for (int p = 0; p < 8; p++) {
        int F = p * 256 + tid;
        int row = F >> 4;
        int c4 = (F & 15) * 4;
        cpa16(dst + row * KSTRIDE + c4, src + (size_t)row * 64 + c4, true);
    }
}

// 64-row tile async copy (activations), OOB rows zero-filled
__device__ __forceinline__ void cpa_tile64(unsigned* dst, const unsigned* __restrict__ src,
                                           int row0, int Mrows, int tid) {
#pragma unroll
    for (int p = 0; p < 4; p++) {
        int F = p * 256 + tid;
        int row = F >> 4;
        int c4 = (F & 15) * 4;
        bool v = (row0 + row) < Mrows;
        cpa16(dst + row * KSTRIDE + c4, src + (size_t)(row0 + row) * 64 + c4, v);
    }
}

// acc += A64 @ W128^T for this warp (64-row A tile)
__device__ __forceinline__ void gemm64(const unsigned* __restrict__ As,
                                       const unsigned* __restrict__ Ws,
                                       float acc[8][4],
                                       int wm, int wn, int g, int t4) {
#pragma unroll
    for (int ks = 0; ks < 8; ks++) {
        int kb = ks * 8;
        int rb = wm * 16;
        unsigned af[4];
        af[0] = As[(rb + g) * KSTRIDE + kb + t4];
        af[1] = As[(rb + 8 + g) * KSTRIDE + kb + t4];
        af[2] = As[(rb + g) * KSTRIDE + kb + t4 + 4];
        af[3] = As[(rb + 8 + g) * KSTRIDE + kb + t4 + 4];
        unsigned bf[8][2];
#pragma unroll
        for (int j = 0; j < 8; j++) {
            int nb = wn * 64 + j * 8;
            bf[j][0] = Ws[(nb + g) * KSTRIDE + kb + t4];
            bf[j][1] = Ws[(nb + g) * KSTRIDE + kb + t4 + 4];
        }
#pragma unroll
        for (int j = 0; j < 8; j++)
            mma_bf16(acc[j], af, bf[j]);
    }
}

// 128-row variant (mlp1)
__device__ __forceinline__ void gemm128(const unsigned* __restrict__ As,
                                        const unsigned* __restrict__ Ws,
                                        float acc[2][8][4],
                                        int wm, int wn, int g, int t4) {
#pragma unroll
    for (int ks = 0; ks < 8; ks++) {
        int kb = ks * 8;
        unsigned af[2][4];
#pragma unroll
        for (int i = 0; i < 2; i++) {
            int rb = wm * 32 + i * 16;
            af[i][0] = As[(rb + g) * KSTRIDE + kb + t4];
            af[i][1] = As[(rb + 8 + g) * KSTRIDE + kb + t4];
            af[i][2] = As[(rb + g) * KSTRIDE + kb + t4 + 4];
            af[i][3] = As[(rb + 8 + g) * KSTRIDE + kb + t4 + 4];
        }
        unsigned bf[8][2];
#pragma unroll
        for (int j = 0; j < 8; j++) {
            int nb = wn * 64 + j * 8;
            bf[j][0] = Ws[(nb + g) * KSTRIDE + kb + t4];
            bf[j][1] = Ws[(nb + g) * KSTRIDE + kb + t4 + 4];
        }
#pragma unroll
        for (int i = 0; i < 2; i++)
#pragma unroll
            for (int j = 0; j < 8; j++)
                mma_bf16(acc[i][j], af[i], bf[j]);
    }
}

__device__ __forceinline__ void zero8(float acc[8][4]) {
#pragma unroll
    for (int j = 0; j < 8; j++)
#pragma unroll
        for (int r = 0; r < 4; r++) acc[j][r] = 0.f;
}

// load 128x128 f32 tile -> bf16 smem (mlp1 features / weights)
__device__ __forceinline__ void load_tile_g(unsigned* dst, const float* __restrict__ src,
                                            int row0, int M, int tid) {
#pragma unroll
    for (int p = 0; p < 16; p++) {
        int F = p * 256 + tid;
        int row = F >> 5, c = F & 31;
        float4 v = make_float4(0.f, 0.f, 0.f, 0.f);
        if (row0 + row < M) v = *reinterpret_cast<const float4*>(src + (size_t)(row0 + row) * HDIM + c * 4);
        dst[row * KSTRIDE + c * 2 + 0] = pack_bf16(v.x, v.y);
        dst[row * KSTRIDE + c * 2 + 1] = pack_bf16(v.z, v.w);
    }
}

__device__ __forceinline__ float sigm(float x) { return 1.f / (1.f + expf(-x)); }

// ---------------- weight prepack ----------------
__global__ void k_pack(const float4* __restrict__ src, uint2* __restrict__ dst, int n4) {
    int i = blockIdx.x * blockDim.x + threadIdx.x;
    if (i < n4) {
        float4 v = src[i];
        dst[i] = make_uint2(pack_bf16(v.x, v.y), pack_bf16(v.z, v.w));
    }
}

// ---------------- CSR build ----------------
__global__ void k_deg_zero(int* deg, int n) {
    int i = blockIdx.x * blockDim.x + threadIdx.x;
    if (i < n) deg[i] = 0;
}

__global__ void k_hist(const int* __restrict__ dst, int* __restrict__ deg, int E) {
    int i = blockIdx.x * blockDim.x + threadIdx.x;
    if (i < E) atomicAdd(&deg[dst[i]], 1);
}

__global__ __launch_bounds__(SCAN_B) void k_scan_local(const int* __restrict__ deg,
                                                       int* __restrict__ rowptr,
                                                       int* __restrict__ blocksum, int n) {
    __shared__ int s[SCAN_B];
    int tid = threadIdx.x;
    int i = blockIdx.x * SCAN_B + tid;
    int v = (i < n) ? deg[i] : 0;
    s[tid] = v;
    __syncthreads();
    for (int off = 1; off < SCAN_B; off <<= 1) {
        int t = (tid >= off) ? s[tid - off] : 0;
        __syncthreads();
        s[tid] += t;
        __syncthreads();
    }
    if (i < n) rowptr[i] = s[tid] - v;
    if (tid == SCAN_B - 1) blocksum[blockIdx.x] = s[tid];
}

__global__ void k_scan_block(const int* __restrict__ blocksum, int* __restrict__ blockoff,
                             int* __restrict__ rowptr, int nblk, int n) {
    if (threadIdx.x == 0 && blockIdx.x == 0) {
        int acc = 0;
        for (int b = 0; b < nblk; b++) { blockoff[b] = acc; acc += blocksum[b]; }
        rowptr[n] = acc;
    }
}

__global__ void k_scan_add(int* __restrict__ rowptr, int* __restrict__ cursor,
                           const int* __restrict__ blockoff, int n) {
    int i = blockIdx.x * blockDim.x + threadIdx.x;
    if (i < n) {
        int v = rowptr[i] + blockoff[i / SCAN_B];
        rowptr[i] = v;
        cursor[i] = v;
    }
}

__global__ void k_scatter(const int* __restrict__ dst, const int* __restrict__ src,
                          const float* __restrict__ ew, int* __restrict__ cursor,
                          int2* __restrict__ csr_e, int E) {
    int i = blockIdx.x * blockDim.x + threadIdx.x;
    if (i < E) {
        int pos = atomicAdd(&cursor[dst[i]], 1);
        csr_e[pos] = make_int2(src[i], __float_as_int(ew[i]));
    }
}

// ---------------- SpMM (CSR, warp per node, 4-edge unrolled bf16 gather) ----------------
__global__ __launch_bounds__(256) void k_spmm_b(
    const int* __restrict__ rowptr, const int2* __restrict__ csr_e,
    const unsigned* __restrict__ xb, unsigned* __restrict__ aggb, int n) {
    int row = (blockIdx.x * blockDim.x + threadIdx.x) >> 5;
    int lane = threadIdx.x & 31;
    if (row >= n) return;
    int e = rowptr[row];
    int end = rowptr[row + 1];
    const uint2* x2 = reinterpret_cast<const uint2*>(xb);
    float a0 = 0.f, a1 = 0.f, a2 = 0.f, a3 = 0.f;
    int e4 = e + ((end - e) & ~3);
    for (; e < e4; e += 4) {
        int2 E0 = csr_e[e];
        int2 E1 = csr_e[e + 1];
        int2 E2 = csr_e[e + 2];
        int2 E3 = csr_e[e + 3];
        uint2 v0 = x2[(size_t)E0.x * 32 + lane];
        uint2 v1 = x2[(size_t)E1.x * 32 + lane];
        uint2 v2 = x2[(size_t)E2.x * 32 + lane];
        uint2 v3 = x2[(size_t)E3.x * 32 + lane];
        float w0 = __int_as_float(E0.y), w1 = __int_as_float(E1.y);
        float w2 = __int_as_float(E2.y), w3 = __int_as_float(E3.y);
        a0 = fmaf(w0, __uint_as_float(v0.x << 16), a0);
        a1 = fmaf(w0, __uint_as_float(v0.x & 0xffff0000u), a1);
        a2 = fmaf(w0, __uint_as_float(v0.y << 16), a2);
        a3 = fmaf(w0, __uint_as_float(v0.y & 0xffff0000u), a3);
        a0 = fmaf(w1, __uint_as_float(v1.x << 16), a0);
        a1 = fmaf(w1, __uint_as_float(v1.x & 0xffff0000u), a1);
        a2 = fmaf(w1, __uint_as_float(v1.y << 16), a2);
        a3 = fmaf(w1, __uint_as_float(v1.y & 0xffff0000u), a3);
        a0 = fmaf(w2, __uint_as_float(v2.x << 16), a0);
        a1 = fmaf(w2, __uint_as_float(v2.x & 0xffff0000u), a1);
        a2 = fmaf(w2, __uint_as_float(v2.y << 16), a2);
        a3 = fmaf(w2, __uint_as_float(v2.y & 0xffff0000u), a3);
        a0 = fmaf(w3, __uint_as_float(v3.x << 16), a0);
        a1 = fmaf(w3, __uint_as_float(v3.x & 0xffff0000u), a1);
        a2 = fmaf(w3, __uint_as_float(v3.y << 16), a2);
        a3 = fmaf(w3, __uint_as_float(v3.y & 0xffff0000u), a3);
    }
    for (; e < end; e++) {
        int2 E0 = csr_e[e];
        float w0 = __int_as_float(E0.y);
        uint2 v0 = x2[(size_t)E0.x * 32 + lane];
        a0 = fmaf(w0, __uint_as_float(v0.x << 16), a0);
        a1 = fmaf(w0, __uint_as_float(v0.x & 0xffff0000u), a1);
        a2 = fmaf(w0, __uint_as_float(v0.y << 16), a2);
        a3 = fmaf(w0, __uint_as_float(v0.y & 0xffff0000u), a3);
    }
    *reinterpret_cast<uint2*>(aggb + (size_t)row * 64 + lane * 2) =
        make_uint2(pack_bf16(a0, a1), pack_bf16(a2, a3));
}

// ---------------- mlp1 GEMM ----------------
__global__ __launch_bounds__(256) void k_gemm_mlp1(
    const float* __restrict__ A, const float* __restrict__ W,
    const float* __restrict__ bias, float* __restrict__ C,
    unsigned* __restrict__ Cb, int M)
{
    extern __shared__ unsigned smem_u[];
    unsigned* As = smem_u;
    unsigned* Ws = smem_u + TILE_U32;

    const int tid = threadIdx.x;
    const int wid = tid >> 5;
    const int lane = tid & 31;
    const int g = lane >> 2;
    const int t4 = lane & 3;
    const int wm = wid & 3;
    const int wn = wid >> 2;
    const int m0 = blockIdx.x * 128;

    load_tile_g(As, A, m0, M, tid);
#pragma unroll
    for (int p = 0; p < 16; p++) {
        int F = p * 256 + tid;
        int row = F >> 5, c = F & 31;
        float4 v = *reinterpret_cast<const float4*>(W + (size_t)row * HDIM + c * 4);
        Ws[row * KSTRIDE + c * 2 + 0] = pack_bf16(v.x, v.y);
        Ws[row * KSTRIDE + c * 2 + 1] = pack_bf16(v.z, v.w);
    }
    __syncthreads();

    float acc[2][8][4];
#pragma unroll
    for (int i = 0; i < 2; i++) zero8(acc[i]);
    gemm128(As, Ws, acc, wm, wn, g, t4);

#pragma unroll
    for (int i = 0; i < 2; i++) {
        int row_lo = m0 + wm * 32 + i * 16 + g;
        int row_hi = row_lo + 8;
#pragma unroll
        for (int j = 0; j < 8; j++) {
            int col = wn * 64 + j * 8 + 2 * t4;
            float b0 = bias[col];
            float b1 = bias[col + 1];
            if (row_lo < M) {
                float v0 = fmaxf(acc[i][j][0] + b0, 0.f);
                float v1 = fmaxf(acc[i][j][1] + b1, 0.f);
                *reinterpret_cast<float2*>(C + (size_t)row_lo * HDIM + col) = make_float2(v0, v1);
                Cb[(size_t)row_lo * 64 + (col >> 1)] = pack_bf16(v0, v1);
            }
            if (row_hi < M) {
                float v2 = fmaxf(acc[i][j][2] + b0, 0.f);
                float v3 = fmaxf(acc[i][j][3] + b1, 0.f);
                *reinterpret_cast<float2*>(C + (size_t)row_hi * HDIM + col) = make_float2(v2, v3);
                Cb[(size_t)row_hi * 64 + (col >> 1)] = pack_bf16(v2, v3);
            }
        }
    }
}
#define GEMM_SMEM (2 * TILE_U32 * 4)

// ---------------- fused GRU (64-row tiles, 2 CTA/SM, 2 live accumulators) ----------------
__global__ __launch_bounds__(256, 2) void k_gru_fused(
    const unsigned* __restrict__ aggb, const unsigned* __restrict__ xb,
    const float* __restrict__ xf,
    const unsigned* __restrict__ wihb, const unsigned* __restrict__ whhb,
    const float* __restrict__ bih, const float* __restrict__ bhh,
    unsigned* __restrict__ hb, int M)
{
    extern __shared__ unsigned sm[];
    unsigned* Aagg = sm;
    unsigned* Ax   = sm + HTILE_U32;
    unsigned* Wb0  = sm + 2 * HTILE_U32;
    unsigned* Wb1  = Wb0 + TILE_U32;

    const int tid = threadIdx.x;
    const int wid = tid >> 5;
    const int lane = tid & 31;
    const int g = lane >> 2;
    const int t4 = lane & 3;
    const int wm = wid & 3;
    const int wn = wid >> 2;
    const int m0 = blockIdx.x * 64;

    // chunk order: c0=whh2, c1=wih0, c2=whh0, c3=wih2, c4=wih1, c5=whh1
    const unsigned* c0 = whhb + 256 * 64;
    const unsigned* c1 = wihb;
    const unsigned* c2 = whhb;
    const unsigned* c3 = wihb + 256 * 64;
    const unsigned* c4 = wihb + 128 * 64;
    const unsigned* c5 = whhb + 128 * 64;

    cpa_tile64(Aagg, aggb, m0, M, tid);
    cpa_tile64(Ax,   xb,   m0, M, tid);
    cpa_tile(Wb0, c0, tid);
    cpa_commit();                      // G0
    cpa_tile(Wb1, c1, tid);
    cpa_commit();                      // G1

    float accA[8][4], accB[8][4];
    zero8(accA); zero8(accB);

    cpa_wait1(); __syncthreads();
    gemm64(Ax, Wb0, accA, wm, wn, g, t4);          // accA = whh2 @ x
    __syncthreads();
    cpa_tile(Wb0, c2, tid); cpa_commit();          // G2

    cpa_wait1(); __syncthreads();
    gemm64(Aagg, Wb1, accB, wm, wn, g, t4);        // accB = wih0 @ agg
    __syncthreads();
    cpa_tile(Wb1, c3, tid); cpa_commit();          // G3

    cpa_wait1(); __syncthreads();
    gemm64(Ax, Wb0, accB, wm, wn, g, t4);          // accB += whh0 @ x  -> r
#pragma unroll
    for (int j = 0; j < 8; j++)
#pragma unroll
        for (int r = 0; r < 4; r++) {
            int col = wn * 64 + j * 8 + 2 * t4 + (r & 1);
            float rv = sigm(accB[j][r] + bih[col] + bhh[col]);
            accA[j][r] = rv * (accA[j][r] + bhh[256 + col]);   // fold r into n path
        }
    __syncthreads();
    cpa_tile(Wb0, c4, tid); cpa_commit();          // G4

    cpa_wait1(); __syncthreads();
    gemm64(Aagg, Wb1, accA, wm, wn, g, t4);        // accA += wih2 @ agg  (n preact)
    __syncthreads();
    cpa_tile(Wb1, c5, tid); cpa_commit();          // G5

    zero8(accB);
    cpa_wait1(); __syncthreads();
    gemm64(Aagg, Wb0, accB, wm, wn, g, t4);        // accB = wih1 @ agg
    cpa_wait0(); __syncthreads();
    gemm64(Ax, Wb1, accB, wm, wn, g, t4);          // accB += whh1 @ x -> z

    // h = (1-z)*tanh(accA + bih2) + z*x
    int row_lo = m0 + wm * 16 + g;
    int row_hi = row_lo + 8;
#pragma unroll
    for (int j = 0; j < 8; j++) {
        int col = wn * 64 + j * 8 + 2 * t4;
        if (row_lo < M) {
            float z0 = sigm(accB[j][0] + bih[128 + col] + bhh[128 + col]);
            float z1 = sigm(accB[j][1] + bih[128 + col + 1] + bhh[128 + col + 1]);
            float2 xv = *reinterpret_cast<const float2*>(xf + (size_t)row_lo * HDIM + col);
            float n0 = tanhf(accA[j][0] + bih[256 + col]);
            float n1 = tanhf(accA[j][1] + bih[256 + col + 1]);
            hb[(size_t)row_lo * 64 + (col >> 1)] =
                pack_bf16((1.f - z0) * n0 + z0 * xv.x, (1.f - z1) * n1 + z1 * xv.y);
        }
        if (row_hi < M) {
            float z2 = sigm(accB[j][2] + bih[128 + col] + bhh[128 + col]);
            float z3 = sigm(accB[j][3] + bih[128 + col + 1] + bhh[128 + col + 1]);
            float2 xv = *reinterpret_cast<const float2*>(xf + (size_t)row_hi * HDIM + col);
            float n2 = tanhf(accA[j][2] + bih[256 + col]);
            float n3 = tanhf(accA[j][3] + bih[256 + col + 1]);
            hb[(size_t)row_hi * 64 + (col >> 1)] =
                pack_bf16((1.f - z2) * n2 + z2 * xv.x, (1.f - z3) * n3 + z3 * xv.y);
        }
    }
}
#define GRU_SMEM ((2 * HTILE_U32 + 2 * TILE_U32) * 4)

// ---------------- fused GIN MLP + norm + head + softmax (64-row tiles) ----------------
template <int C>
__global__ __launch_bounds__(256, 2) void k_gin_head(
    const unsigned* __restrict__ hbt,
    const unsigned* __restrict__ g1b, const float* __restrict__ b1v,
    const unsigned* __restrict__ g2b, const float* __restrict__ b2v,
    const unsigned* __restrict__ hw1b, const float* __restrict__ hb1,
    const float* __restrict__ w2, const float* __restrict__ bh2,
    float* __restrict__ xout, unsigned* __restrict__ xbout,
    float* __restrict__ olog, float* __restrict__ osoft,
    int M)
{
    extern __shared__ unsigned sm[];
    unsigned* Ah   = sm;                          // h tile / later x tile
    unsigned* At1  = sm + HTILE_U32;              // t1 / t2 / logits (aliased)
    unsigned* Wb0  = sm + 2 * HTILE_U32;          // g1 -> hw1
    unsigned* Wb1  = Wb0 + TILE_U32;              // g2
    unsigned* W2s  = Wb1 + TILE_U32;              // head w2 (24 rows)
    float* rowsum  = reinterpret_cast<float*>(W2s + 24 * KSTRIDE);  // [64]

    const int tid = threadIdx.x;
    const int wid = tid >> 5;
    const int lane = tid & 31;
    const int g = lane >> 2;
    const int t4 = lane & 3;
    const int wm = wid & 3;
    const int wn = wid >> 2;
    const int m0 = blockIdx.x * 64;

    if (tid < 64) rowsum[tid] = 0.f;
    cpa_tile64(Ah, hbt, m0, M, tid);
    cpa_tile(Wb0, g1b, tid);
    cpa_commit();                      // G0
    cpa_tile(Wb1, g2b, tid);
    cpa_commit();                      // G1

    float acc[8][4];

    // ---- t1 = relu(h @ g1^T + b1) ----
    zero8(acc);
    cpa_wait1(); __syncthreads();
    gemm64(Ah, Wb0, acc, wm, wn, g, t4);
    {
        int rl = wm * 16 + g;
#pragma unroll
        for (int j = 0; j < 8; j++) {
            int col = wn * 64 + j * 8 + 2 * t4;
            At1[rl * KSTRIDE + (col >> 1)] =
                pack_bf16(fmaxf(acc[j][0] + b1v[col], 0.f), fmaxf(acc[j][1] + b1v[col + 1], 0.f));
            At1[(rl + 8) * KSTRIDE + (col >> 1)] =
                pack_bf16(fmaxf(acc[j][2] + b1v[col], 0.f), fmaxf(acc[j][3] + b1v[col + 1], 0.f));
        }
    }
    __syncthreads();
    cpa_tile(Wb0, hw1b, tid); cpa_commit();        // G2

    // ---- x = relu(t1 @ g2^T + b2), rowsum ----
    zero8(acc);
    cpa_wait1(); __syncthreads();
    gemm64(At1, Wb1, acc, wm, wn, g, t4);
    {
        float s_lo = 0.f, s_hi = 0.f;
#pragma unroll
        for (int j = 0; j < 8; j++) {
            int col = wn * 64 + j * 8 + 2 * t4;
            acc[j][0] = fmaxf(acc[j][0] + b2v[col], 0.f);
            acc[j][1] = fmaxf(acc[j][1] + b2v[col + 1], 0.f);
            acc[j][2] = fmaxf(acc[j][2] + b2v[col], 0.f);
            acc[j][3] = fmaxf(acc[j][3] + b2v[col + 1], 0.f);
            s_lo += acc[j][0] * acc[j][0] + acc[j][1] * acc[j][1];
            s_hi += acc[j][2] * acc[j][2] + acc[j][3] * acc[j][3];
        }
        atomicAdd(&rowsum[wm * 16 + g], s_lo);
        atomicAdd(&rowsum[wm * 16 + 8 + g], s_hi);
    }
    __syncthreads();

    // ---- normalize, write x (f32 + bf16), repack to Ah; load W2s ----
    {
        int rl = wm * 16 + g;
        float inv_lo = rsqrtf(1.f + rowsum[rl]);
        float inv_hi = rsqrtf(1.f + rowsum[rl + 8]);
        int gm_lo = m0 + rl;
        int gm_hi = gm_lo + 8;
#pragma unroll
        for (int j = 0; j < 8; j++) {
            int col = wn * 64 + j * 8 + 2 * t4;
            float v0 = acc[j][0] * inv_lo;
            float v1 = acc[j][1] * inv_lo;
            float v2 = acc[j][2] * inv_hi;
            float v3 = acc[j][3] * inv_hi;
            unsigned p_lo = pack_bf16(v0, v1);
            unsigned p_hi = pack_bf16(v2, v3);
            Ah[rl * KSTRIDE + (col >> 1)] = p_lo;
            Ah[(rl + 8) * KSTRIDE + (col >> 1)] = p_hi;
            if (gm_lo < M) {
                *reinterpret_cast<float2*>(xout + (size_t)gm_lo * HDIM + col) = make_float2(v0, v1);
                xbout[(size_t)gm_lo * 64 + (col >> 1)] = p_lo;
            }
            if (gm_hi < M) {
                *reinterpret_cast<float2*>(xout + (size_t)gm_hi * HDIM + col) = make_float2(v2, v3);
                xbout[(size_t)gm_hi * 64 + (col >> 1)] = p_hi;
            }
        }
    }
    for (int idx = tid; idx < 24 * 32; idx += 256) {
        int row = idx >> 5, c = idx & 31;
        float4 v = make_float4(0.f, 0.f, 0.f, 0.f);
        if (row < C) v = *reinterpret_cast<const float4*>(w2 + (size_t)row * HDIM + c * 4);
        W2s[row * KSTRIDE + c * 2 + 0] = pack_bf16(v.x, v.y);
        W2s[row * KSTRIDE + c * 2 + 1] = pack_bf16(v.z, v.w);
    }
    __syncthreads();

    // ---- t2 = relu(x @ hw1^T + hb1) -> At1 ----
    zero8(acc);
    cpa_wait0(); __syncthreads();
    gemm64(Ah, Wb0, acc, wm, wn, g, t4);
    {
        int rl = wm * 16 + g;
#pragma unroll
        for (int j = 0; j < 8; j++) {
            int col = wn * 64 + j * 8 + 2 * t4;
            At1[rl * KSTRIDE + (col >> 1)] =
                pack_bf16(fmaxf(acc[j][0] + hb1[col], 0.f), fmaxf(acc[j][1] + hb1[col + 1], 0.f));
            At1[(rl + 8) * KSTRIDE + (col >> 1)] =
                pack_bf16(fmaxf(acc[j][2] + hb1[col], 0.f), fmaxf(acc[j][3] + hb1[col + 1], 0.f));
        }
    }
    __syncthreads();

    // ---- head logits: t2 @ w2^T (warps with wn==0 cover all 64 rows) ----
    float hacc[3][4];
#pragma unroll
    for (int j = 0; j < 3; j++)
#pragma unroll
        for (int r = 0; r < 4; r++) hacc[j][r] = 0.f;
    if (wn == 0) {
#pragma unroll
        for (int ks = 0; ks < 8; ks++) {
            int kb = ks * 8;
            int rb = wm * 16;
            unsigned af[4];
            af[0] = At1[(rb + g) * KSTRIDE + kb + t4];
            af[1] = At1[(rb + 8 + g) * KSTRIDE + kb + t4];
            af[2] = At1[(rb + g) * KSTRIDE + kb + t4 + 4];
            af[3] = At1[(rb + 8 + g) * KSTRIDE + kb + t4 + 4];
            unsigned bfr[3][2];
#pragma unroll
            for (int j = 0; j < 3; j++) {
                int nb = j * 8;
                bfr[j][0] = W2s[(nb + g) * KSTRIDE + kb + t4];
                bfr[j][1] = W2s[(nb + g) * KSTRIDE + kb + t4 + 4];
            }
#pragma unroll
            for (int j = 0; j < 3; j++)
                mma_bf16(hacc[j], af, bfr[j]);
        }
    }
    __syncthreads();                 // all reads of At1 complete
    float* logitp = reinterpret_cast<float*>(At1);   // [64][28]
    if (wn == 0) {
        int rl = wm * 16 + g;
#pragma unroll
        for (int j = 0; j < 3; j++) {
            int col = j * 8 + 2 * t4;
            logitp[rl * 28 + col] = hacc[j][0];
            logitp[rl * 28 + col + 1] = hacc[j][1];
            logitp[(rl + 8) * 28 + col] = hacc[j][2];
            logitp[(rl + 8) * 28 + col + 1] = hacc[j][3];
        }
    }
    __syncthreads();

    // ---- softmax / log_softmax (8 nodes per warp) ----
#pragma unroll
    for (int k = 0; k < 8; k++) {
        int nl = wid * 8 + k;
        int gm = m0 + nl;
        float myval = (lane < C) ? (logitp[nl * 28 + lane] + bh2[lane]) : 0.f;
        float mx = (lane < C) ? myval : -INFINITY;
#pragma unroll
        for (int o = 16; o; o >>= 1) mx = fmaxf(mx, __shfl_xor_sync(0xffffffffu, mx, o));
        float e = (lane < C) ? expf(myval - mx) : 0.f;
        float s = e;
#pragma unroll
        for (int o = 16; o; o >>= 1) s += __shfl_xor_sync(0xffffffffu, s, o);
        if (gm < M && lane < C) {
            olog [(size_t)gm * C + lane] = myval - mx - logf(s);
            osoft[(size_t)gm * C + lane] = e / s;
        }
    }
}
#define GIN_SMEM ((2 * HTILE_U32 + 2 * TILE_U32 + 24 * KSTRIDE + 64) * 4)

// ---------------- launch ----------------
extern "C" void kernel_launch(void* const* d_in, const int* in_sizes, int n_in,
                              void* d_out, int out_size) {
    const float* features = (const float*)d_in[0];
    const int*   eidx     = (const int*)  d_in[1];
    const float* ew       = (const float*)d_in[2];
    const float* w1       = (const float*)d_in[3];
    const float* b1       = (const float*)d_in[4];
    const float* gin_w1   = (const float*)d_in[5];
    const float* gin_b1   = (const float*)d_in[6];
    const float* gin_w2   = (const float*)d_in[7];
    const float* gin_b2   = (const float*)d_in[8];
    const float* gru_wih  = (const float*)d_in[9];
    const float* gru_whh  = (const float*)d_in[10];
    const float* gru_bih  = (const float*)d_in[11];
    const float* gru_bhh  = (const float*)d_in[12];
    const float* head_w1  = (const float*)d_in[13];
    const float* head_b1  = (const float*)d_in[14];
    const float* hw2_0    = (const float*)d_in[15];
    const float* hb2_0    = (const float*)d_in[16];
    const float* hw2_1    = (const float*)d_in[17];
    const float* hb2_1    = (const float*)d_in[18];
    const float* hw2_2    = (const float*)d_in[19];
    const float* hb2_2    = (const float*)d_in[20];

    float* out = (float*)d_out;

    float *p_x;
    unsigned *p_xb, *p_aggb, *p_hb, *p_wb;
    int2 *p_csr_e;
    int *p_rowptr, *p_cursor, *p_bsum, *p_boff;
    cudaGetSymbolAddress((void**)&p_x,      g_x);
    cudaGetSymbolAddress((void**)&p_xb,     g_xb);
    cudaGetSymbolAddress((void**)&p_aggb,   g_aggb);
    cudaGetSymbolAddress((void**)&p_hb,     g_hb);
    cudaGetSymbolAddress((void**)&p_wb,     g_wb);
    cudaGetSymbolAddress((void**)&p_rowptr, g_rowptr);
    cudaGetSymbolAddress((void**)&p_cursor, g_cursor);
    cudaGetSymbolAddress((void**)&p_bsum,   g_blocksum);
    cudaGetSymbolAddress((void**)&p_boff,   g_blockoff);
    cudaGetSymbolAddress((void**)&p_csr_e,  g_csr_e);

    cudaFuncSetAttribute(k_gemm_mlp1,    cudaFuncAttributeMaxDynamicSharedMemorySize, GEMM_SMEM);
    cudaFuncSetAttribute(k_gru_fused,    cudaFuncAttributeMaxDynamicSharedMemorySize, GRU_SMEM);
    cudaFuncSetAttribute(k_gin_head<2>,  cudaFuncAttributeMaxDynamicSharedMemorySize, GIN_SMEM);
    cudaFuncSetAttribute(k_gin_head<6>,  cudaFuncAttributeMaxDynamicSharedMemorySize, GIN_SMEM);
    cudaFuncSetAttribute(k_gin_head<21>, cudaFuncAttributeMaxDynamicSharedMemorySize, GIN_SMEM);

    const int M = NNODES;
    const int E = NEDGES;
    const int tile_gx   = (M + 127) / 128;   // 782
    const int tile64_gx = (M + 63) / 64;     // 1563
    const int warp_blocks = (M * 32 + 255) / 256;
    const int edge_blocks = (E + 255) / 256;
    const int node_blocks = (M + 255) / 256;

    const int* e_dst = eidx;
    const int* e_src = eidx + E;

    const size_t o_log0 = 0;
    const size_t o_log1 = (size_t)M * 2;
    const size_t o_log2 = (size_t)M * 8;
    const size_t o_soft = (size_t)M * 29;

    // ---- prepack weights to bf16 ----
    {
        int n4;
        n4 = 3 * 384 * HDIM / 4;
        k_pack<<<(n4 + 255) / 256, 256>>>((const float4*)gru_wih, (uint2*)(p_wb + OFF_WIH), n4);
        k_pack<<<(n4 + 255) / 256, 256>>>((const float4*)gru_whh, (uint2*)(p_wb + OFF_WHH), n4);
        n4 = 3 * HDIM * HDIM / 4;
        k_pack<<<(n4 + 255) / 256, 256>>>((const float4*)gin_w1,  (uint2*)(p_wb + OFF_GW1), n4);
        k_pack<<<(n4 + 255) / 256, 256>>>((const float4*)gin_w2,  (uint2*)(p_wb + OFF_GW2), n4);
        k_pack<<<(n4 + 255) / 256, 256>>>((const float4*)head_w1, (uint2*)(p_wb + OFF_HW1), n4);
    }

    // ---- build CSR ----
    k_deg_zero<<<node_blocks, 256>>>(p_cursor, M);
    k_hist<<<edge_blocks, 256>>>(e_dst, p_cursor, E);
    k_scan_local<<<NSCANB, SCAN_B>>>(p_cursor, p_rowptr, p_bsum, M);
    k_scan_block<<<1, 32>>>(p_bsum, p_boff, p_rowptr, NSCANB, M);
    k_scan_add<<<node_blocks, 256>>>(p_rowptr, p_cursor, p_boff, M);
    k_scatter<<<edge_blocks, 256>>>(e_dst, e_src, ew, p_cursor, p_csr_e, E);

    // x = relu(features @ w1^T + b1)
    k_gemm_mlp1<<<tile_gx, 256, GEMM_SMEM>>>(features, w1, b1, p_x, p_xb, M);

    for (int i = 0; i < NL; i++) {
        k_spmm_b<<<warp_blocks, 256>>>(p_rowptr, p_csr_e, p_xb, p_aggb, M);

        k_gru_fused<<<tile64_gx, 256, GRU_SMEM>>>(
            p_aggb, p_xb, p_x,
            p_wb + OFF_WIH + (size_t)i * 384 * 64,
            p_wb + OFF_WHH + (size_t)i * 384 * 64,
            gru_bih + (size_t)i * 384, gru_bhh + (size_t)i * 384,
            p_hb, M);

        const unsigned* g1b  = p_wb + OFF_GW1 + (size_t)i * 128 * 64;
        const unsigned* g2b  = p_wb + OFF_GW2 + (size_t)i * 128 * 64;
        const unsigned* hw1b = p_wb + OFF_HW1 + (size_t)i * 128 * 64;
        if (i == 0)
            k_gin_head<2><<<tile64_gx, 256, GIN_SMEM>>>(
                p_hb, g1b, gin_b1, g2b, gin_b2,
                hw1b, head_b1, hw2_0, hb2_0,
                p_x, p_xb, out + o_log0, out + o_soft, M);
        else if (i == 1)
            k_gin_head<6><<<tile64_gx, 256, GIN_SMEM>>>(
                p_hb, g1b, gin_b1 + HDIM, g2b, gin_b2 + HDIM,
                hw1b, head_b1 + HDIM, hw2_1, hb2_1,
                p_x, p_xb, out + o_log1, out + o_soft + (size_t)M * 2, M);
        else
            k_gin_head<21><<<tile64_gx, 256, GIN_SMEM>>>(
                p_hb, g1b, gin_b1 + 2 * HDIM, g2b, gin_b2 + 2 * HDIM,
                hw1b, head_b1 + 2 * HDIM, hw2_2, hb2_2,
                p_x, p_xb, out + o_log2, out + o_soft + (size_t)M * 8, M);
    }
}